// round 7
// baseline (speedup 1.0000x reference)
#include <cuda_runtime.h>
#include <cuda_bf16.h>
#include <math.h>
#include <stdint.h>

#define BB   128
#define TT   256
#define IN   512
#define HH   1024
#define OUT  512
#define NG   4096
#define INH  1536
#define KC   64
#define SPAD 72      // smem row stride in bf16 (64 + 8 pad)
#define NBLK 128     // persistent grid size (<= 148 SMs, all co-resident)

// ---------------- static device scratch (~153 MB) -----------------------------
__device__ __nv_bfloat16 g_Wrhi[(size_t)NG * INH];   // reordered: r = bx*32 + gate*8 + jl
__device__ __nv_bfloat16 g_Wrlo[(size_t)NG * INH];
__device__ float         g_biasr[NG];
__device__ __nv_bfloat16 g_hshi[(size_t)BB * TT * HH];   // [b][t][j]
__device__ __nv_bfloat16 g_hslo[(size_t)BB * TT * HH];
__device__ unsigned      g_bar_count;
__device__ unsigned      g_bar_gen;

__device__ __forceinline__ float sigm(float v) { return 1.f / (1.f + expf(-v)); }

__device__ __forceinline__ void mma_bf16(float* c, const uint32_t* a, const uint32_t* b) {
    asm volatile(
        "mma.sync.aligned.m16n8k16.row.col.f32.bf16.bf16.f32 "
        "{%0,%1,%2,%3}, {%4,%5,%6,%7}, {%8,%9}, {%0,%1,%2,%3};"
        : "+f"(c[0]), "+f"(c[1]), "+f"(c[2]), "+f"(c[3])
        : "r"(a[0]), "r"(a[1]), "r"(a[2]), "r"(a[3]), "r"(b[0]), "r"(b[1]));
}

// pack 8 fp32 -> hi uint4 (8 bf16) + lo uint4
__device__ __forceinline__ void split8(const float4 f0, const float4 f1,
                                       uint4& hi, uint4& lo)
{
    const float v[8] = {f0.x, f0.y, f0.z, f0.w, f1.x, f1.y, f1.z, f1.w};
    __nv_bfloat16 h[8], l[8];
    #pragma unroll
    for (int i = 0; i < 8; i++) {
        h[i] = __float2bfloat16(v[i]);
        l[i] = __float2bfloat16(v[i] - __bfloat162float(h[i]));
    }
    hi = *(const uint4*)h;
    lo = *(const uint4*)l;
}

// ---------------- conversion kernels -----------------------------------------
__global__ void conv_w(const float* __restrict__ Wf, const float* __restrict__ Wi,
                       const float* __restrict__ Wc, const float* __restrict__ Wo)
{
    size_t idx = (size_t)blockIdx.x * 256 + threadIdx.x;   // over NG*INH
    int r = (int)(idx / INH);
    int k = (int)(idx - (size_t)r * INH);
    int bx   = r >> 5;
    int gate = (r >> 3) & 3;
    int jl   = r & 7;
    int j    = bx * 8 + jl;
    const float* W = (gate == 0) ? Wf : (gate == 1) ? Wi : (gate == 2) ? Wc : Wo;
    float v = W[(size_t)j * INH + k];
    __nv_bfloat16 hi = __float2bfloat16(v);
    g_Wrhi[idx] = hi;
    g_Wrlo[idx] = __float2bfloat16(v - __bfloat162float(hi));
}

__global__ void conv_bias(const float* __restrict__ bf, const float* __restrict__ bi,
                          const float* __restrict__ bc, const float* __restrict__ bo)
{
    int r = blockIdx.x * 256 + threadIdx.x;
    if (r < NG) {
        int bx = r >> 5, gate = (r >> 3) & 3, jl = r & 7;
        int j = bx * 8 + jl;
        const float* b = (gate == 0) ? bf : (gate == 1) ? bi : (gate == 2) ? bc : bo;
        g_biasr[r] = b[j];
    }
}

// ---------------- staged chunk registers --------------------------------------
struct Stage {
    uint4 avh[8], avl[8];
    uint4 bvh0, bvh1, bvl0, bvl1;
};

__device__ __forceinline__ void load_chunk(Stage& s, const float* __restrict__ x,
                                           int t, int k0, int tid, int brow, int bq, int n0)
{
    if (k0 < IN) {
        const float* xp = x + ((size_t)tid * TT + t) * IN + k0;
        #pragma unroll
        for (int q = 0; q < 8; q++) {
            const float4 f0 = *(const float4*)(xp + q * 8);
            const float4 f1 = *(const float4*)(xp + q * 8 + 4);
            split8(f0, f1, s.avh[q], s.avl[q]);
        }
    } else {
        // h planes: bypass L1 (written by other SMs within this launch)
        const size_t abase = ((size_t)tid * TT + (t - 1)) * HH + (k0 - IN);
        #pragma unroll
        for (int q = 0; q < 8; q++) {
            s.avh[q] = __ldcg((const uint4*)(g_hshi + abase + q * 8));
            s.avl[q] = __ldcg((const uint4*)(g_hslo + abase + q * 8));
        }
    }
    const size_t bbase = (size_t)(n0 + brow) * INH + k0;
    s.bvh0 = *(const uint4*)(g_Wrhi + bbase + bq * 8);
    s.bvh1 = *(const uint4*)(g_Wrhi + bbase + bq * 8 + 8);
    s.bvl0 = *(const uint4*)(g_Wrlo + bbase + bq * 8);
    s.bvl1 = *(const uint4*)(g_Wrlo + bbase + bq * 8 + 8);
}

// ---------------- persistent recurrent kernel --------------------------------
// grid = 128 blocks x 128 threads, all co-resident. Block bx: all 128 batch
// rows x 32 gate cols (c = gate*8+jl; j = bx*8+jl). Loops t = 0..255 with a
// software grid barrier between steps. c-state lives in registers.
__global__ void __launch_bounds__(128) k_persist(const float* __restrict__ x)
{
    __shared__ __nv_bfloat16 Ah[128][SPAD], Al[128][SPAD];
    __shared__ __nv_bfloat16 Bh[32][SPAD],  Bl[32][SPAD];
    __shared__ float bias_s[32];

    const int tid  = threadIdx.x;
    const int w    = tid >> 5;
    const int lane = tid & 31;
    const int g    = lane >> 2;
    const int t2   = lane & 3;
    const int n0   = blockIdx.x * 32;
    const int j0   = blockIdx.x * 8;
    const int brow = tid >> 2;
    const int bq   = (tid & 3) * 2;

    if (tid < 32) bias_s[tid] = g_biasr[n0 + tid];

    float creg[2][2][2];        // [mt][dr][dc] cell state, persistent across t
    #pragma unroll
    for (int a = 0; a < 2; a++)
        #pragma unroll
        for (int b = 0; b < 2; b++)
            #pragma unroll
            for (int d = 0; d < 2; d++) creg[a][b][d] = 0.f;

    Stage st;

    for (int t = 0; t < TT; t++) {
        const int nch = (t == 0) ? (IN / KC) : (INH / KC);

        float acc[2][4][4];
        #pragma unroll
        for (int mt = 0; mt < 2; mt++)
            #pragma unroll
            for (int nt = 0; nt < 4; nt++)
                #pragma unroll
                for (int i = 0; i < 4; i++) acc[mt][nt][i] = 0.f;

        // prologue: stage chunk 0
        load_chunk(st, x, t, 0, tid, brow, bq, n0);

        for (int c_ = 0; c_ < nch; c_++) {
            __syncthreads();        // previous chunk's frag reads done
            #pragma unroll
            for (int q = 0; q < 8; q++) {
                *(uint4*)&Ah[tid][q * 8] = st.avh[q];
                *(uint4*)&Al[tid][q * 8] = st.avl[q];
            }
            *(uint4*)&Bh[brow][bq * 8]       = st.bvh0;
            *(uint4*)&Bh[brow][(bq + 1) * 8] = st.bvh1;
            *(uint4*)&Bl[brow][bq * 8]       = st.bvl0;
            *(uint4*)&Bl[brow][(bq + 1) * 8] = st.bvl1;
            __syncthreads();

            // issue NEXT chunk's gmem loads; they fly during the mma below
            if (c_ + 1 < nch)
                load_chunk(st, x, t, (c_ + 1) * KC, tid, brow, bq, n0);

            #pragma unroll
            for (int ks = 0; ks < 4; ks++) {
                const int kb = ks * 16 + 2 * t2;
                uint32_t ah[2][4], al[2][4];
                #pragma unroll
                for (int mt = 0; mt < 2; mt++) {
                    const int r = w * 32 + mt * 16;
                    ah[mt][0] = *(const uint32_t*)&Ah[r + g][kb];
                    ah[mt][1] = *(const uint32_t*)&Ah[r + g + 8][kb];
                    ah[mt][2] = *(const uint32_t*)&Ah[r + g][kb + 8];
                    ah[mt][3] = *(const uint32_t*)&Ah[r + g + 8][kb + 8];
                    al[mt][0] = *(const uint32_t*)&Al[r + g][kb];
                    al[mt][1] = *(const uint32_t*)&Al[r + g + 8][kb];
                    al[mt][2] = *(const uint32_t*)&Al[r + g][kb + 8];
                    al[mt][3] = *(const uint32_t*)&Al[r + g + 8][kb + 8];
                }
                #pragma unroll
                for (int nt = 0; nt < 4; nt++) {
                    uint32_t bh[2], bl[2];
                    bh[0] = *(const uint32_t*)&Bh[nt * 8 + g][kb];
                    bh[1] = *(const uint32_t*)&Bh[nt * 8 + g][kb + 8];
                    bl[0] = *(const uint32_t*)&Bl[nt * 8 + g][kb];
                    bl[1] = *(const uint32_t*)&Bl[nt * 8 + g][kb + 8];
                    #pragma unroll
                    for (int mt = 0; mt < 2; mt++) {
                        mma_bf16(acc[mt][nt], ah[mt], bh);
                        mma_bf16(acc[mt][nt], ah[mt], bl);
                        mma_bf16(acc[mt][nt], al[mt], bh);
                    }
                }
            }
        }

        // ---- fused LSTM cell epilogue ----
        #pragma unroll
        for (int mt = 0; mt < 2; mt++) {
            #pragma unroll
            for (int dr = 0; dr < 2; dr++) {
                const int b_  = w * 32 + mt * 16 + g + dr * 8;
                const int ci0 = dr * 2;
                const int jlA = 2 * t2;

                float hn2[2];
                #pragma unroll
                for (int dc = 0; dc < 2; dc++) {
                    const int jl = jlA + dc;
                    const int ci = ci0 + dc;
                    const float fp = acc[mt][0][ci] + bias_s[jl];
                    const float ip = acc[mt][1][ci] + bias_s[8 + jl];
                    const float cp = acc[mt][2][ci] + bias_s[16 + jl];
                    const float op = acc[mt][3][ci] + bias_s[24 + jl];
                    const float cn = sigm(fp) * creg[mt][dr][dc] + sigm(ip) * tanhf(cp);
                    creg[mt][dr][dc] = cn;
                    hn2[dc] = sigm(op) * tanhf(cn);
                }
                const size_t ho = ((size_t)b_ * TT + t) * HH + j0 + jlA;
                __nv_bfloat16 h0 = __float2bfloat16(hn2[0]);
                __nv_bfloat16 h1 = __float2bfloat16(hn2[1]);
                __nv_bfloat162 hhi; hhi.x = h0; hhi.y = h1;
                __nv_bfloat162 hlo;
                hlo.x = __float2bfloat16(hn2[0] - __bfloat162float(h0));
                hlo.y = __float2bfloat16(hn2[1] - __bfloat162float(h1));
                *(__nv_bfloat162*)(g_hshi + ho) = hhi;
                *(__nv_bfloat162*)(g_hslo + ho) = hlo;
            }
        }

        // ---- grid barrier (h of step t visible before step t+1 reads it) ----
        if (t < TT - 1) {
            __threadfence();
            __syncthreads();
            if (tid == 0) {
                const unsigned gen = atomicAdd(&g_bar_gen, 0u);
                if (atomicAdd(&g_bar_count, 1u) == NBLK - 1) {
                    atomicExch(&g_bar_count, 0u);
                    __threadfence();
                    atomicAdd(&g_bar_gen, 1u);
                } else {
                    while (atomicAdd(&g_bar_gen, 0u) == gen) {}
                }
            }
            __syncthreads();
        }
    }
}

// ---------------- kernel 3: out = hs @ W_out^T + b_out (fp32 SIMT) -----------
__global__ void __launch_bounds__(256, 2) k3_out(
                       const float* __restrict__ Wout,
                       const float* __restrict__ bout,
                       float* __restrict__ out)
{
    __shared__ float As[8][128];
    __shared__ float Bs[8][128];

    const int m0 = blockIdx.x * 128;
    const int n0 = blockIdx.y * 128;
    const int tid = threadIdx.x;
    const int lr = tid >> 1;
    const int lk = (tid & 1) * 4;

    const __nv_bfloat16* Ahp = g_hshi + (size_t)(m0 + lr) * HH;
    const __nv_bfloat16* Alp = g_hslo + (size_t)(m0 + lr) * HH;
    const float* Brow = Wout + (size_t)(n0 + lr) * HH;

    float acc[8][8];
    #pragma unroll
    for (int i = 0; i < 8; i++)
        #pragma unroll
        for (int j = 0; j < 8; j++) acc[i][j] = 0.f;

    const int r0 = (tid >> 4) * 8;
    const int c0 = (tid & 15) * 8;

    for (int k0 = 0; k0 < HH; k0 += 8) {
        const uint2 rh = *(const uint2*)(Ahp + k0 + lk);
        const uint2 rl = *(const uint2*)(Alp + k0 + lk);
        const __nv_bfloat162 h01 = *(const __nv_bfloat162*)&rh.x;
        const __nv_bfloat162 h23 = *(const __nv_bfloat162*)&rh.y;
        const __nv_bfloat162 l01 = *(const __nv_bfloat162*)&rl.x;
        const __nv_bfloat162 l23 = *(const __nv_bfloat162*)&rl.y;
        float4 av;
        av.x = __bfloat162float(h01.x) + __bfloat162float(l01.x);
        av.y = __bfloat162float(h01.y) + __bfloat162float(l01.y);
        av.z = __bfloat162float(h23.x) + __bfloat162float(l23.x);
        av.w = __bfloat162float(h23.y) + __bfloat162float(l23.y);
        const float4 bv = *(const float4*)(Brow + k0 + lk);
        __syncthreads();
        As[lk + 0][lr] = av.x; As[lk + 1][lr] = av.y; As[lk + 2][lr] = av.z; As[lk + 3][lr] = av.w;
        Bs[lk + 0][lr] = bv.x; Bs[lk + 1][lr] = bv.y; Bs[lk + 2][lr] = bv.z; Bs[lk + 3][lr] = bv.w;
        __syncthreads();
        #pragma unroll
        for (int k = 0; k < 8; k++) {
            float4 a0 = *(const float4*)&As[k][r0];
            float4 a1 = *(const float4*)&As[k][r0 + 4];
            float4 b0 = *(const float4*)&Bs[k][c0];
            float4 b1 = *(const float4*)&Bs[k][c0 + 4];
            float ar[8] = {a0.x, a0.y, a0.z, a0.w, a1.x, a1.y, a1.z, a1.w};
            float br[8] = {b0.x, b0.y, b0.z, b0.w, b1.x, b1.y, b1.z, b1.w};
            #pragma unroll
            for (int i = 0; i < 8; i++)
                #pragma unroll
                for (int j = 0; j < 8; j++) acc[i][j] += ar[i] * br[j];
        }
    }

    #pragma unroll
    for (int i = 0; i < 8; i++) {
        float* Crow = out + (size_t)(m0 + r0 + i) * OUT + n0;
        #pragma unroll
        for (int j = 0; j < 8; j++) Crow[c0 + j] = acc[i][j] + bout[n0 + c0 + j];
    }
}

// ---------------- launch -----------------------------------------------------
extern "C" void kernel_launch(void* const* d_in, const int* in_sizes, int n_in,
                              void* d_out, int out_size)
{
    const float* x    = (const float*)d_in[0];
    const float* Wf   = (const float*)d_in[1];
    const float* bf   = (const float*)d_in[2];
    const float* Wi   = (const float*)d_in[3];
    const float* bi   = (const float*)d_in[4];
    const float* Wc   = (const float*)d_in[5];
    const float* bc   = (const float*)d_in[6];
    const float* Wo   = (const float*)d_in[7];
    const float* bo   = (const float*)d_in[8];
    const float* Wout = (const float*)d_in[9];
    const float* bout = (const float*)d_in[10];
    float* out = (float*)d_out;

    conv_w   <<<(NG * INH) / 256, 256>>>(Wf, Wi, Wc, Wo);
    conv_bias<<<16, 256>>>(bf, bi, bc, bo);

    k_persist<<<NBLK, 128>>>(x);

    k3_out<<<dim3((BB * TT) / 128, OUT / 128), 256>>>(Wout, bout, out);
}

// round 8
// speedup vs baseline: 1.2551x; 1.2551x over previous
#include <cuda_runtime.h>
#include <cuda_bf16.h>
#include <math.h>
#include <stdint.h>

#define BB   128
#define TT   256
#define IN   512
#define HH   1024
#define OUT  512
#define NG   4096
#define INH  1536
#define KC   64
#define SPAD 72        // smem row stride in bf16 (64 + 8 pad)
#define NBLK 128       // persistent grid (1 block/SM, co-resident)

// dynamic smem stage layout (bytes)
#define ST_A_H 0
#define ST_A_L 18432                 // 128*72*2
#define ST_B_H 36864
#define ST_B_L 41472                 // +32*72*2
#define STAGE  46080
#define SMEM_DYN (2 * STAGE)         // 92160

// ---------------- static device scratch (~153 MB) -----------------------------
__device__ __nv_bfloat16 g_Wrhi[(size_t)NG * INH];   // r = bx*32 + gate*8 + jl
__device__ __nv_bfloat16 g_Wrlo[(size_t)NG * INH];
__device__ float         g_biasr[NG];
__device__ __nv_bfloat16 g_hshi[(size_t)BB * TT * HH];   // [b][t][j]
__device__ __nv_bfloat16 g_hslo[(size_t)BB * TT * HH];
__device__ unsigned      g_bar_count;
__device__ unsigned      g_bar_gen;

__device__ __forceinline__ float sigm(float v) { return 1.f / (1.f + expf(-v)); }

__device__ __forceinline__ void mma_bf16(float* c, const uint32_t* a, const uint32_t* b) {
    asm volatile(
        "mma.sync.aligned.m16n8k16.row.col.f32.bf16.bf16.f32 "
        "{%0,%1,%2,%3}, {%4,%5,%6,%7}, {%8,%9}, {%0,%1,%2,%3};"
        : "+f"(c[0]), "+f"(c[1]), "+f"(c[2]), "+f"(c[3])
        : "r"(a[0]), "r"(a[1]), "r"(a[2]), "r"(a[3]), "r"(b[0]), "r"(b[1]));
}

__device__ __forceinline__ void split8(const float4 f0, const float4 f1,
                                       uint4& hi, uint4& lo)
{
    const float v[8] = {f0.x, f0.y, f0.z, f0.w, f1.x, f1.y, f1.z, f1.w};
    __nv_bfloat16 h[8], l[8];
    #pragma unroll
    for (int i = 0; i < 8; i++) {
        h[i] = __float2bfloat16(v[i]);
        l[i] = __float2bfloat16(v[i] - __bfloat162float(h[i]));
    }
    hi = *(const uint4*)h;
    lo = *(const uint4*)l;
}

// ---------------- conversion kernels -----------------------------------------
__global__ void conv_w(const float* __restrict__ Wf, const float* __restrict__ Wi,
                       const float* __restrict__ Wc, const float* __restrict__ Wo)
{
    size_t idx = (size_t)blockIdx.x * 256 + threadIdx.x;   // over NG*INH
    int r = (int)(idx / INH);
    int k = (int)(idx - (size_t)r * INH);
    int bx   = r >> 5;
    int gate = (r >> 3) & 3;
    int jl   = r & 7;
    int j    = bx * 8 + jl;
    const float* W = (gate == 0) ? Wf : (gate == 1) ? Wi : (gate == 2) ? Wc : Wo;
    float v = W[(size_t)j * INH + k];
    __nv_bfloat16 hi = __float2bfloat16(v);
    g_Wrhi[idx] = hi;
    g_Wrlo[idx] = __float2bfloat16(v - __bfloat162float(hi));
}

__global__ void conv_bias(const float* __restrict__ bf, const float* __restrict__ bi,
                          const float* __restrict__ bc, const float* __restrict__ bo)
{
    int r = blockIdx.x * 256 + threadIdx.x;
    if (r < NG) {
        int bx = r >> 5, gate = (r >> 3) & 3, jl = r & 7;
        int j = bx * 8 + jl;
        const float* b = (gate == 0) ? bf : (gate == 1) ? bi : (gate == 2) ? bc : bo;
        g_biasr[r] = b[j];
    }
}

// ---------------- staged chunk registers --------------------------------------
struct Stage {
    uint4 avh[4], avl[4];   // A: 32 elems (4 uint4) per plane per thread
    uint4 bvh, bvl;         // B: 8 elems per plane per thread
};

// 256-thread staging maps:
//   A: row = tid>>1 (0..127), quad base aq0 = (tid&1)*4  (cols [aq0*8, aq0*8+32))
//   B: row = tid>>3 (0..31),  quad bq = tid&7            (cols [bq*8, bq*8+8))
__device__ __forceinline__ void load_chunk(Stage& s, const float* __restrict__ x,
                                           int t, int k0, int arow, int aq0,
                                           int brow, int bq, int n0)
{
    if (k0 < IN) {
        const float* xp = x + ((size_t)arow * TT + t) * IN + k0 + aq0 * 8;
        #pragma unroll
        for (int q = 0; q < 4; q++) {
            const float4 f0 = *(const float4*)(xp + q * 8);
            const float4 f1 = *(const float4*)(xp + q * 8 + 4);
            split8(f0, f1, s.avh[q], s.avl[q]);
        }
    } else {
        const size_t abase = ((size_t)arow * TT + (t - 1)) * HH + (k0 - IN) + aq0 * 8;
        #pragma unroll
        for (int q = 0; q < 4; q++) {
            s.avh[q] = __ldcg((const uint4*)(g_hshi + abase + q * 8));
            s.avl[q] = __ldcg((const uint4*)(g_hslo + abase + q * 8));
        }
    }
    const size_t bbase = (size_t)(n0 + brow) * INH + k0 + bq * 8;
    s.bvh = *(const uint4*)(g_Wrhi + bbase);
    s.bvl = *(const uint4*)(g_Wrlo + bbase);
}

__device__ __forceinline__ void store_stage(const Stage& s, char* buf,
                                            int arow, int aq0, int brow, int bq)
{
    #pragma unroll
    for (int q = 0; q < 4; q++) {
        *(uint4*)(buf + ST_A_H + (arow * SPAD + (aq0 + q) * 8) * 2) = s.avh[q];
        *(uint4*)(buf + ST_A_L + (arow * SPAD + (aq0 + q) * 8) * 2) = s.avl[q];
    }
    *(uint4*)(buf + ST_B_H + (brow * SPAD + bq * 8) * 2) = s.bvh;
    *(uint4*)(buf + ST_B_L + (brow * SPAD + bq * 8) * 2) = s.bvl;
}

// ---------------- persistent recurrent kernel --------------------------------
// grid = 128 x 256. Block bx: all 128 batch rows x 32 gate cols
// (c = gate*8 + jl; j = bx*8 + jl). Warp w: rows [16w, 16w+16), all 32 cols.
// Double-buffered K chunks of 64; software grid barrier between steps.
__global__ void __launch_bounds__(256, 1) k_persist(const float* __restrict__ x)
{
    extern __shared__ char smem[];
    __shared__ float bias_s[32];

    const int tid  = threadIdx.x;
    const int w    = tid >> 5;
    const int lane = tid & 31;
    const int g    = lane >> 2;
    const int t2   = lane & 3;
    const int n0   = blockIdx.x * 32;
    const int j0   = blockIdx.x * 8;
    const int arow = tid >> 1;
    const int aq0  = (tid & 1) * 4;
    const int brow = tid >> 3;
    const int bq   = tid & 7;

    if (tid < 32) bias_s[tid] = g_biasr[n0 + tid];
    __syncthreads();

    float creg[2][2];          // [dr][dc] cell state, persistent across t
    creg[0][0] = creg[0][1] = creg[1][0] = creg[1][1] = 0.f;

    Stage st;

    for (int t = 0; t < TT; t++) {
        const int nch = (t == 0) ? (IN / KC) : (INH / KC);

        float acc[4][4];
        #pragma unroll
        for (int nt = 0; nt < 4; nt++)
            #pragma unroll
            for (int i = 0; i < 4; i++) acc[nt][i] = 0.f;

        // pipeline prologue: chunk 0 -> buf0, chunk 1 -> regs
        load_chunk(st, x, t, 0, arow, aq0, brow, bq, n0);
        store_stage(st, smem, arow, aq0, brow, bq);          // buf0 safe: sync'd at t-1 end
        load_chunk(st, x, t, KC, arow, aq0, brow, bq, n0);
        __syncthreads();

        int p = 0;
        for (int c_ = 0; c_ < nch; c_++) {
            // stage chunk c+1 into the other buffer; kick off chunk c+2 loads
            if (c_ + 1 < nch) {
                store_stage(st, smem + (1 - p) * STAGE, arow, aq0, brow, bq);
                if (c_ + 2 < nch)
                    load_chunk(st, x, t, (c_ + 2) * KC, arow, aq0, brow, bq, n0);
            }

            // ---- MMA on buf[p] ----
            const char* buf = smem + p * STAGE;
            #pragma unroll
            for (int ks = 0; ks < 4; ks++) {
                const int kb = ks * 16 + 2 * t2;
                const int r  = w * 16;
                uint32_t ah[4], al[4];
                ah[0] = *(const uint32_t*)(buf + ST_A_H + ((r + g)     * SPAD + kb)     * 2);
                ah[1] = *(const uint32_t*)(buf + ST_A_H + ((r + g + 8) * SPAD + kb)     * 2);
                ah[2] = *(const uint32_t*)(buf + ST_A_H + ((r + g)     * SPAD + kb + 8) * 2);
                ah[3] = *(const uint32_t*)(buf + ST_A_H + ((r + g + 8) * SPAD + kb + 8) * 2);
                al[0] = *(const uint32_t*)(buf + ST_A_L + ((r + g)     * SPAD + kb)     * 2);
                al[1] = *(const uint32_t*)(buf + ST_A_L + ((r + g + 8) * SPAD + kb)     * 2);
                al[2] = *(const uint32_t*)(buf + ST_A_L + ((r + g)     * SPAD + kb + 8) * 2);
                al[3] = *(const uint32_t*)(buf + ST_A_L + ((r + g + 8) * SPAD + kb + 8) * 2);
                #pragma unroll
                for (int nt = 0; nt < 4; nt++) {
                    uint32_t bh[2], bl[2];
                    bh[0] = *(const uint32_t*)(buf + ST_B_H + ((nt * 8 + g) * SPAD + kb)     * 2);
                    bh[1] = *(const uint32_t*)(buf + ST_B_H + ((nt * 8 + g) * SPAD + kb + 8) * 2);
                    bl[0] = *(const uint32_t*)(buf + ST_B_L + ((nt * 8 + g) * SPAD + kb)     * 2);
                    bl[1] = *(const uint32_t*)(buf + ST_B_L + ((nt * 8 + g) * SPAD + kb + 8) * 2);
                    mma_bf16(acc[nt], ah, bh);
                    mma_bf16(acc[nt], ah, bl);
                    mma_bf16(acc[nt], al, bh);
                }
            }
            __syncthreads();
            p ^= 1;
        }

        // ---- fused LSTM cell epilogue (warp w owns rows [16w,16w+16)) ----
        #pragma unroll
        for (int dr = 0; dr < 2; dr++) {
            const int b_  = w * 16 + g + dr * 8;
            const int ci0 = dr * 2;
            const int jlA = 2 * t2;

            float hn2[2];
            #pragma unroll
            for (int dc = 0; dc < 2; dc++) {
                const int jl = jlA + dc;
                const int ci = ci0 + dc;
                const float fp = acc[0][ci] + bias_s[jl];
                const float ip = acc[1][ci] + bias_s[8 + jl];
                const float cp = acc[2][ci] + bias_s[16 + jl];
                const float op = acc[3][ci] + bias_s[24 + jl];
                const float cn = sigm(fp) * creg[dr][dc] + sigm(ip) * tanhf(cp);
                creg[dr][dc] = cn;
                hn2[dc] = sigm(op) * tanhf(cn);
            }
            const size_t ho = ((size_t)b_ * TT + t) * HH + j0 + jlA;
            __nv_bfloat16 h0 = __float2bfloat16(hn2[0]);
            __nv_bfloat16 h1 = __float2bfloat16(hn2[1]);
            __nv_bfloat162 hhi; hhi.x = h0; hhi.y = h1;
            __nv_bfloat162 hlo;
            hlo.x = __float2bfloat16(hn2[0] - __bfloat162float(h0));
            hlo.y = __float2bfloat16(hn2[1] - __bfloat162float(h1));
            *(__nv_bfloat162*)(g_hshi + ho) = hhi;
            *(__nv_bfloat162*)(g_hslo + ho) = hlo;
        }

        // ---- grid barrier ----
        if (t < TT - 1) {
            __threadfence();
            __syncthreads();
            if (tid == 0) {
                const unsigned gen = *(volatile unsigned*)&g_bar_gen;
                if (atomicAdd(&g_bar_count, 1u) == NBLK - 1) {
                    g_bar_count = 0;
                    __threadfence();
                    atomicAdd(&g_bar_gen, 1u);
                } else {
                    while (*(volatile unsigned*)&g_bar_gen == gen) {}
                }
            }
            __syncthreads();
        }
    }
}

// ---------------- kernel 3: out = hs @ W_out^T + b_out (fp32 SIMT) -----------
__global__ void __launch_bounds__(256, 2) k3_out(
                       const float* __restrict__ Wout,
                       const float* __restrict__ bout,
                       float* __restrict__ out)
{
    __shared__ float As[8][128];
    __shared__ float Bs[8][128];

    const int m0 = blockIdx.x * 128;
    const int n0 = blockIdx.y * 128;
    const int tid = threadIdx.x;
    const int lr = tid >> 1;
    const int lk = (tid & 1) * 4;

    const __nv_bfloat16* Ahp = g_hshi + (size_t)(m0 + lr) * HH;
    const __nv_bfloat16* Alp = g_hslo + (size_t)(m0 + lr) * HH;
    const float* Brow = Wout + (size_t)(n0 + lr) * HH;

    float acc[8][8];
    #pragma unroll
    for (int i = 0; i < 8; i++)
        #pragma unroll
        for (int j = 0; j < 8; j++) acc[i][j] = 0.f;

    const int r0 = (tid >> 4) * 8;
    const int c0 = (tid & 15) * 8;

    for (int k0 = 0; k0 < HH; k0 += 8) {
        const uint2 rh = *(const uint2*)(Ahp + k0 + lk);
        const uint2 rl = *(const uint2*)(Alp + k0 + lk);
        const __nv_bfloat162 h01 = *(const __nv_bfloat162*)&rh.x;
        const __nv_bfloat162 h23 = *(const __nv_bfloat162*)&rh.y;
        const __nv_bfloat162 l01 = *(const __nv_bfloat162*)&rl.x;
        const __nv_bfloat162 l23 = *(const __nv_bfloat162*)&rl.y;
        float4 av;
        av.x = __bfloat162float(h01.x) + __bfloat162float(l01.x);
        av.y = __bfloat162float(h01.y) + __bfloat162float(l01.y);
        av.z = __bfloat162float(h23.x) + __bfloat162float(l23.x);
        av.w = __bfloat162float(h23.y) + __bfloat162float(l23.y);
        const float4 bv = *(const float4*)(Brow + k0 + lk);
        __syncthreads();
        As[lk + 0][lr] = av.x; As[lk + 1][lr] = av.y; As[lk + 2][lr] = av.z; As[lk + 3][lr] = av.w;
        Bs[lk + 0][lr] = bv.x; Bs[lk + 1][lr] = bv.y; Bs[lk + 2][lr] = bv.z; Bs[lk + 3][lr] = bv.w;
        __syncthreads();
        #pragma unroll
        for (int k = 0; k < 8; k++) {
            float4 a0 = *(const float4*)&As[k][r0];
            float4 a1 = *(const float4*)&As[k][r0 + 4];
            float4 b0 = *(const float4*)&Bs[k][c0];
            float4 b1 = *(const float4*)&Bs[k][c0 + 4];
            float ar[8] = {a0.x, a0.y, a0.z, a0.w, a1.x, a1.y, a1.z, a1.w};
            float br[8] = {b0.x, b0.y, b0.z, b0.w, b1.x, b1.y, b1.z, b1.w};
            #pragma unroll
            for (int i = 0; i < 8; i++)
                #pragma unroll
                for (int j = 0; j < 8; j++) acc[i][j] += ar[i] * br[j];
        }
    }

    #pragma unroll
    for (int i = 0; i < 8; i++) {
        float* Crow = out + (size_t)(m0 + r0 + i) * OUT + n0;
        #pragma unroll
        for (int j = 0; j < 8; j++) Crow[c0 + j] = acc[i][j] + bout[n0 + c0 + j];
    }
}

// ---------------- launch -----------------------------------------------------
extern "C" void kernel_launch(void* const* d_in, const int* in_sizes, int n_in,
                              void* d_out, int out_size)
{
    const float* x    = (const float*)d_in[0];
    const float* Wf   = (const float*)d_in[1];
    const float* bf   = (const float*)d_in[2];
    const float* Wi   = (const float*)d_in[3];
    const float* bi   = (const float*)d_in[4];
    const float* Wc   = (const float*)d_in[5];
    const float* bc   = (const float*)d_in[6];
    const float* Wo   = (const float*)d_in[7];
    const float* bo   = (const float*)d_in[8];
    const float* Wout = (const float*)d_in[9];
    const float* bout = (const float*)d_in[10];
    float* out = (float*)d_out;

    cudaFuncSetAttribute(k_persist, cudaFuncAttributeMaxDynamicSharedMemorySize, SMEM_DYN);

    conv_w   <<<(NG * INH) / 256, 256>>>(Wf, Wi, Wc, Wo);
    conv_bias<<<16, 256>>>(bf, bi, bc, bo);

    k_persist<<<NBLK, 256, SMEM_DYN>>>(x);

    k3_out<<<dim3((BB * TT) / 128, OUT / 128), 256>>>(Wout, bout, out);
}

// round 9
// speedup vs baseline: 1.3256x; 1.0562x over previous
#include <cuda_runtime.h>
#include <cuda_bf16.h>
#include <math.h>
#include <stdint.h>

#define BB   128
#define TT   256
#define IN   512
#define HH   1024
#define OUT  512
#define NG   4096
#define INH  1536
#define KC   64
#define SPAD 72        // smem row stride in bf16 (64 + 8 pad)
#define NBLK 128       // persistent grid (1 block/SM, co-resident)
#define NCH_X (IN / KC)            // 8 x-chunks
#define NCH_H ((INH - IN) / KC)    // 16 h-chunks

// dynamic smem stage layout (bytes)
#define ST_A_H 0
#define ST_A_L 18432                 // 128*72*2
#define ST_B_H 36864
#define ST_B_L 41472                 // +32*72*2
#define STAGE  46080
#define SMEM_DYN (2 * STAGE)         // 92160

// ---------------- static device scratch (~153 MB) -----------------------------
__device__ __nv_bfloat16 g_Wrhi[(size_t)NG * INH];   // r = bx*32 + gate*8 + jl
__device__ __nv_bfloat16 g_Wrlo[(size_t)NG * INH];
__device__ float         g_biasr[NG];
__device__ __nv_bfloat16 g_hshi[(size_t)BB * TT * HH];   // [b][t][j]
__device__ __nv_bfloat16 g_hslo[(size_t)BB * TT * HH];
__device__ unsigned      g_bar_count;
__device__ unsigned      g_bar_gen;

__device__ __forceinline__ float sigm(float v) { return 1.f / (1.f + expf(-v)); }

__device__ __forceinline__ void mma_bf16(float* c, const uint32_t* a, const uint32_t* b) {
    asm volatile(
        "mma.sync.aligned.m16n8k16.row.col.f32.bf16.bf16.f32 "
        "{%0,%1,%2,%3}, {%4,%5,%6,%7}, {%8,%9}, {%0,%1,%2,%3};"
        : "+f"(c[0]), "+f"(c[1]), "+f"(c[2]), "+f"(c[3])
        : "r"(a[0]), "r"(a[1]), "r"(a[2]), "r"(a[3]), "r"(b[0]), "r"(b[1]));
}

__device__ __forceinline__ void split8(const float4 f0, const float4 f1,
                                       uint4& hi, uint4& lo)
{
    const float v[8] = {f0.x, f0.y, f0.z, f0.w, f1.x, f1.y, f1.z, f1.w};
    __nv_bfloat16 h[8], l[8];
    #pragma unroll
    for (int i = 0; i < 8; i++) {
        h[i] = __float2bfloat16(v[i]);
        l[i] = __float2bfloat16(v[i] - __bfloat162float(h[i]));
    }
    hi = *(const uint4*)h;
    lo = *(const uint4*)l;
}

// ---------------- conversion kernels -----------------------------------------
__global__ void conv_w(const float* __restrict__ Wf, const float* __restrict__ Wi,
                       const float* __restrict__ Wc, const float* __restrict__ Wo)
{
    size_t idx = (size_t)blockIdx.x * 256 + threadIdx.x;   // over NG*INH
    int r = (int)(idx / INH);
    int k = (int)(idx - (size_t)r * INH);
    int bx   = r >> 5;
    int gate = (r >> 3) & 3;
    int jl   = r & 7;
    int j    = bx * 8 + jl;
    const float* W = (gate == 0) ? Wf : (gate == 1) ? Wi : (gate == 2) ? Wc : Wo;
    float v = W[(size_t)j * INH + k];
    __nv_bfloat16 hi = __float2bfloat16(v);
    g_Wrhi[idx] = hi;
    g_Wrlo[idx] = __float2bfloat16(v - __bfloat162float(hi));
}

__global__ void conv_bias(const float* __restrict__ bf, const float* __restrict__ bi,
                          const float* __restrict__ bc, const float* __restrict__ bo)
{
    int r = blockIdx.x * 256 + threadIdx.x;
    if (r < NG) {
        int bx = r >> 5, gate = (r >> 3) & 3, jl = r & 7;
        int j = bx * 8 + jl;
        const float* b = (gate == 0) ? bf : (gate == 1) ? bi : (gate == 2) ? bc : bo;
        g_biasr[r] = b[j];
    }
}

// ---------------- staged chunk registers --------------------------------------
struct Stage {
    uint4 avh[4], avl[4];   // A: 32 elems (4 uint4) per plane per thread
    uint4 bvh, bvl;         // B: 8 elems per plane per thread
};

// 256-thread staging maps:
//   A: row = tid>>1 (0..127), quad base aq0 = (tid&1)*4
//   B: row = tid>>3 (0..31),  quad bq = tid&7
__device__ __forceinline__ void load_chunk(Stage& s, const float* __restrict__ x,
                                           int t, int k0, int arow, int aq0,
                                           int brow, int bq, int n0)
{
    if (k0 < IN) {
        const float* xp = x + ((size_t)arow * TT + t) * IN + k0 + aq0 * 8;
        #pragma unroll
        for (int q = 0; q < 4; q++) {
            const float4 f0 = *(const float4*)(xp + q * 8);
            const float4 f1 = *(const float4*)(xp + q * 8 + 4);
            split8(f0, f1, s.avh[q], s.avl[q]);
        }
    } else {
        const size_t abase = ((size_t)arow * TT + (t - 1)) * HH + (k0 - IN) + aq0 * 8;
        #pragma unroll
        for (int q = 0; q < 4; q++) {
            s.avh[q] = __ldcg((const uint4*)(g_hshi + abase + q * 8));
            s.avl[q] = __ldcg((const uint4*)(g_hslo + abase + q * 8));
        }
    }
    const size_t bbase = (size_t)(n0 + brow) * INH + k0 + bq * 8;
    s.bvh = *(const uint4*)(g_Wrhi + bbase);
    s.bvl = *(const uint4*)(g_Wrlo + bbase);
}

__device__ __forceinline__ void store_stage(const Stage& s, char* buf,
                                            int arow, int aq0, int brow, int bq)
{
    #pragma unroll
    for (int q = 0; q < 4; q++) {
        *(uint4*)(buf + ST_A_H + (arow * SPAD + (aq0 + q) * 8) * 2) = s.avh[q];
        *(uint4*)(buf + ST_A_L + (arow * SPAD + (aq0 + q) * 8) * 2) = s.avl[q];
    }
    *(uint4*)(buf + ST_B_H + (brow * SPAD + bq * 8) * 2) = s.bvh;
    *(uint4*)(buf + ST_B_L + (brow * SPAD + bq * 8) * 2) = s.bvl;
}

// one double-buffered phase over nch chunks starting at k_base
__device__ __forceinline__ void run_phase(char* smem, const float* __restrict__ x,
                                          int t, int k_base, int nch,
                                          int arow, int aq0, int brow, int bq,
                                          int n0, int w, int g, int t2,
                                          Stage& st, float acc[4][4])
{
    load_chunk(st, x, t, k_base, arow, aq0, brow, bq, n0);
    store_stage(st, smem, arow, aq0, brow, bq);
    if (nch > 1) load_chunk(st, x, t, k_base + KC, arow, aq0, brow, bq, n0);
    __syncthreads();

    int p = 0;
    for (int c_ = 0; c_ < nch; c_++) {
        if (c_ + 1 < nch) {
            store_stage(st, smem + (1 - p) * STAGE, arow, aq0, brow, bq);
            if (c_ + 2 < nch)
                load_chunk(st, x, t, k_base + (c_ + 2) * KC, arow, aq0, brow, bq, n0);
        }
        const char* buf = smem + p * STAGE;
        #pragma unroll
        for (int ks = 0; ks < 4; ks++) {
            const int kb = ks * 16 + 2 * t2;
            const int r  = w * 16;
            uint32_t ah[4], al[4];
            ah[0] = *(const uint32_t*)(buf + ST_A_H + ((r + g)     * SPAD + kb)     * 2);
            ah[1] = *(const uint32_t*)(buf + ST_A_H + ((r + g + 8) * SPAD + kb)     * 2);
            ah[2] = *(const uint32_t*)(buf + ST_A_H + ((r + g)     * SPAD + kb + 8) * 2);
            ah[3] = *(const uint32_t*)(buf + ST_A_H + ((r + g + 8) * SPAD + kb + 8) * 2);
            al[0] = *(const uint32_t*)(buf + ST_A_L + ((r + g)     * SPAD + kb)     * 2);
            al[1] = *(const uint32_t*)(buf + ST_A_L + ((r + g + 8) * SPAD + kb)     * 2);
            al[2] = *(const uint32_t*)(buf + ST_A_L + ((r + g)     * SPAD + kb + 8) * 2);
            al[3] = *(const uint32_t*)(buf + ST_A_L + ((r + g + 8) * SPAD + kb + 8) * 2);
            #pragma unroll
            for (int nt = 0; nt < 4; nt++) {
                uint32_t bh[2], bl[2];
                bh[0] = *(const uint32_t*)(buf + ST_B_H + ((nt * 8 + g) * SPAD + kb)     * 2);
                bh[1] = *(const uint32_t*)(buf + ST_B_H + ((nt * 8 + g) * SPAD + kb + 8) * 2);
                bl[0] = *(const uint32_t*)(buf + ST_B_L + ((nt * 8 + g) * SPAD + kb)     * 2);
                bl[1] = *(const uint32_t*)(buf + ST_B_L + ((nt * 8 + g) * SPAD + kb + 8) * 2);
                mma_bf16(acc[nt], ah, bh);
                mma_bf16(acc[nt], ah, bl);
                mma_bf16(acc[nt], al, bh);
            }
        }
        __syncthreads();
        p ^= 1;
    }
}

// ---------------- persistent recurrent kernel --------------------------------
// grid = 128 x 256, co-resident. Block bx: 128 batch rows x 32 gate cols.
// Split arrive/wait grid barrier: after writing h_t, blocks arrive (non-
// blocking), compute the x-chunks of step t+1 (independent of h_t), THEN wait.
__global__ void __launch_bounds__(256, 1) k_persist(const float* __restrict__ x)
{
    extern __shared__ char smem[];
    __shared__ float bias_s[32];

    const int tid  = threadIdx.x;
    const int w    = tid >> 5;
    const int lane = tid & 31;
    const int g    = lane >> 2;
    const int t2   = lane & 3;
    const int n0   = blockIdx.x * 32;
    const int j0   = blockIdx.x * 8;
    const int arow = tid >> 1;
    const int aq0  = (tid & 1) * 4;
    const int brow = tid >> 3;
    const int bq   = tid & 7;

    if (tid < 32) bias_s[tid] = g_biasr[n0 + tid];
    __syncthreads();

    float creg[2][2];
    creg[0][0] = creg[0][1] = creg[1][0] = creg[1][1] = 0.f;

    Stage st;
    unsigned gen_cap = 0;     // meaningful on tid 0 only

    for (int t = 0; t < TT; t++) {
        float acc[4][4];
        #pragma unroll
        for (int nt = 0; nt < 4; nt++)
            #pragma unroll
            for (int i = 0; i < 4; i++) acc[nt][i] = 0.f;

        // ---- X phase (independent of h_{t-1}; overlaps the barrier wait) ----
        run_phase(smem, x, t, 0, NCH_X, arow, aq0, brow, bq, n0, w, g, t2, st, acc);

        if (t > 0) {
            // ---- wait: all blocks have written h_{t-1} ----
            if (tid == 0) {
                while (*(volatile unsigned*)&g_bar_gen == gen_cap) {}
            }
            __syncthreads();
            // ---- H phase ----
            run_phase(smem, x, t, IN, NCH_H, arow, aq0, brow, bq, n0, w, g, t2, st, acc);
        }

        // ---- fused LSTM cell epilogue ----
        #pragma unroll
        for (int dr = 0; dr < 2; dr++) {
            const int b_  = w * 16 + g + dr * 8;
            const int ci0 = dr * 2;
            const int jlA = 2 * t2;

            float hn2[2];
            #pragma unroll
            for (int dc = 0; dc < 2; dc++) {
                const int jl = jlA + dc;
                const int ci = ci0 + dc;
                const float fp = acc[0][ci] + bias_s[jl];
                const float ip = acc[1][ci] + bias_s[8 + jl];
                const float cp = acc[2][ci] + bias_s[16 + jl];
                const float op = acc[3][ci] + bias_s[24 + jl];
                const float cn = sigm(fp) * creg[dr][dc] + sigm(ip) * tanhf(cp);
                creg[dr][dc] = cn;
                hn2[dc] = sigm(op) * tanhf(cn);
            }
            const size_t ho = ((size_t)b_ * TT + t) * HH + j0 + jlA;
            __nv_bfloat16 h0 = __float2bfloat16(hn2[0]);
            __nv_bfloat16 h1 = __float2bfloat16(hn2[1]);
            __nv_bfloat162 hhi; hhi.x = h0; hhi.y = h1;
            __nv_bfloat162 hlo;
            hlo.x = __float2bfloat16(hn2[0] - __bfloat162float(h0));
            hlo.y = __float2bfloat16(hn2[1] - __bfloat162float(h1));
            __stcg((unsigned*)(g_hshi + ho), *(const unsigned*)&hhi);
            __stcg((unsigned*)(g_hslo + ho), *(const unsigned*)&hlo);
        }

        // ---- arrive (non-blocking); wait happens after next X phase ----
        if (t < TT - 1) {
            __threadfence();
            __syncthreads();
            if (tid == 0) {
                gen_cap = *(volatile unsigned*)&g_bar_gen;   // capture BEFORE arriving
                if (atomicAdd(&g_bar_count, 1u) == NBLK - 1) {
                    g_bar_count = 0;
                    __threadfence();
                    atomicAdd(&g_bar_gen, 1u);
                }
            }
            // no block-wide wait here: other warps roll into the next X phase
        }
    }
}

// ---------------- kernel 3: out = hs @ W_out^T + b_out (fp32 SIMT) -----------
__global__ void __launch_bounds__(256, 2) k3_out(
                       const float* __restrict__ Wout,
                       const float* __restrict__ bout,
                       float* __restrict__ out)
{
    __shared__ float As[8][128];
    __shared__ float Bs[8][128];

    const int m0 = blockIdx.x * 128;
    const int n0 = blockIdx.y * 128;
    const int tid = threadIdx.x;
    const int lr = tid >> 1;
    const int lk = (tid & 1) * 4;

    const __nv_bfloat16* Ahp = g_hshi + (size_t)(m0 + lr) * HH;
    const __nv_bfloat16* Alp = g_hslo + (size_t)(m0 + lr) * HH;
    const float* Brow = Wout + (size_t)(n0 + lr) * HH;

    float acc[8][8];
    #pragma unroll
    for (int i = 0; i < 8; i++)
        #pragma unroll
        for (int j = 0; j < 8; j++) acc[i][j] = 0.f;

    const int r0 = (tid >> 4) * 8;
    const int c0 = (tid & 15) * 8;

    for (int k0 = 0; k0 < HH; k0 += 8) {
        const uint2 rh = *(const uint2*)(Ahp + k0 + lk);
        const uint2 rl = *(const uint2*)(Alp + k0 + lk);
        const __nv_bfloat162 h01 = *(const __nv_bfloat162*)&rh.x;
        const __nv_bfloat162 h23 = *(const __nv_bfloat162*)&rh.y;
        const __nv_bfloat162 l01 = *(const __nv_bfloat162*)&rl.x;
        const __nv_bfloat162 l23 = *(const __nv_bfloat162*)&rl.y;
        float4 av;
        av.x = __bfloat162float(h01.x) + __bfloat162float(l01.x);
        av.y = __bfloat162float(h01.y) + __bfloat162float(l01.y);
        av.z = __bfloat162float(h23.x) + __bfloat162float(l23.x);
        av.w = __bfloat162float(h23.y) + __bfloat162float(l23.y);
        const float4 bv = *(const float4*)(Brow + k0 + lk);
        __syncthreads();
        As[lk + 0][lr] = av.x; As[lk + 1][lr] = av.y; As[lk + 2][lr] = av.z; As[lk + 3][lr] = av.w;
        Bs[lk + 0][lr] = bv.x; Bs[lk + 1][lr] = bv.y; Bs[lk + 2][lr] = bv.z; Bs[lk + 3][lr] = bv.w;
        __syncthreads();
        #pragma unroll
        for (int k = 0; k < 8; k++) {
            float4 a0 = *(const float4*)&As[k][r0];
            float4 a1 = *(const float4*)&As[k][r0 + 4];
            float4 b0 = *(const float4*)&Bs[k][c0];
            float4 b1 = *(const float4*)&Bs[k][c0 + 4];
            float ar[8] = {a0.x, a0.y, a0.z, a0.w, a1.x, a1.y, a1.z, a1.w};
            float br[8] = {b0.x, b0.y, b0.z, b0.w, b1.x, b1.y, b1.z, b1.w};
            #pragma unroll
            for (int i = 0; i < 8; i++)
                #pragma unroll
                for (int j = 0; j < 8; j++) acc[i][j] += ar[i] * br[j];
        }
    }

    #pragma unroll
    for (int i = 0; i < 8; i++) {
        float* Crow = out + (size_t)(m0 + r0 + i) * OUT + n0;
        #pragma unroll
        for (int j = 0; j < 8; j++) Crow[c0 + j] = acc[i][j] + bout[n0 + c0 + j];
    }
}

// ---------------- launch -----------------------------------------------------
extern "C" void kernel_launch(void* const* d_in, const int* in_sizes, int n_in,
                              void* d_out, int out_size)
{
    const float* x    = (const float*)d_in[0];
    const float* Wf   = (const float*)d_in[1];
    const float* bf   = (const float*)d_in[2];
    const float* Wi   = (const float*)d_in[3];
    const float* bi   = (const float*)d_in[4];
    const float* Wc   = (const float*)d_in[5];
    const float* bc   = (const float*)d_in[6];
    const float* Wo   = (const float*)d_in[7];
    const float* bo   = (const float*)d_in[8];
    const float* Wout = (const float*)d_in[9];
    const float* bout = (const float*)d_in[10];
    float* out = (float*)d_out;

    cudaFuncSetAttribute(k_persist, cudaFuncAttributeMaxDynamicSharedMemorySize, SMEM_DYN);

    conv_w   <<<(NG * INH) / 256, 256>>>(Wf, Wi, Wc, Wo);
    conv_bias<<<16, 256>>>(bf, bi, bc, bo);

    k_persist<<<NBLK, 256, SMEM_DYN>>>(x);

    k3_out<<<dim3((BB * TT) / 128, OUT / 128), 256>>>(Wout, bout, out);
}

// round 10
// speedup vs baseline: 1.6250x; 1.2259x over previous
#include <cuda_runtime.h>
#include <cuda_bf16.h>
#include <math.h>
#include <stdint.h>

#define BB   128
#define TT   256
#define IN   512
#define HH   1024
#define OUT  512
#define NG   4096
#define INH  1536
#define KC   64
#define SPAD 72        // smem row stride in bf16 (64 + 8 pad) -> 144B, conflict-free
#define NBLK 128       // persistent grid (1 block/SM, co-resident)

// stage layout (bytes)
#define ST_A_H 0
#define ST_A_L 18432                 // 128*72*2
#define ST_B_H 36864                 // +128*72*2
#define ST_B_L 41472                 // +32*72*2
#define STAGE  46080
#define NSTAGE 4
#define SMEM_DYN (NSTAGE * STAGE)    // 184320

// ---------------- static device scratch (~153 MB) -----------------------------
__device__ __nv_bfloat16 g_Wrhi[(size_t)NG * INH];   // r = bx*32 + gate*8 + jl
__device__ __nv_bfloat16 g_Wrlo[(size_t)NG * INH];
__device__ float         g_biasr[NG];
__device__ __nv_bfloat16 g_hshi[(size_t)BB * TT * HH];   // [b][t][j]
__device__ __nv_bfloat16 g_hslo[(size_t)BB * TT * HH];
__device__ unsigned      g_bar_count;
__device__ unsigned      g_bar_gen;

__device__ __forceinline__ float sigm(float v) { return 1.f / (1.f + expf(-v)); }

__device__ __forceinline__ void mma_bf16(float* c, const uint32_t* a, const uint32_t* b) {
    asm volatile(
        "mma.sync.aligned.m16n8k16.row.col.f32.bf16.bf16.f32 "
        "{%0,%1,%2,%3}, {%4,%5,%6,%7}, {%8,%9}, {%0,%1,%2,%3};"
        : "+f"(c[0]), "+f"(c[1]), "+f"(c[2]), "+f"(c[3])
        : "r"(a[0]), "r"(a[1]), "r"(a[2]), "r"(a[3]), "r"(b[0]), "r"(b[1]));
}

__device__ __forceinline__ void ldm4(uint32_t* r, uint32_t addr) {
    asm volatile("ldmatrix.sync.aligned.m8n8.x4.shared.b16 {%0,%1,%2,%3}, [%4];"
        : "=r"(r[0]), "=r"(r[1]), "=r"(r[2]), "=r"(r[3]) : "r"(addr));
}

__device__ __forceinline__ void cpa(uint32_t dst, const void* src) {
    asm volatile("cp.async.cg.shared.global [%0], [%1], 16;" :: "r"(dst), "l"(src));
}
#define CP_COMMIT() asm volatile("cp.async.commit_group;")
#define CP_WAIT2()  asm volatile("cp.async.wait_group 2;")

// ---------------- conversion kernels -----------------------------------------
__global__ void conv_w(const float* __restrict__ Wf, const float* __restrict__ Wi,
                       const float* __restrict__ Wc, const float* __restrict__ Wo)
{
    size_t idx = (size_t)blockIdx.x * 256 + threadIdx.x;   // over NG*INH
    int r = (int)(idx / INH);
    int k = (int)(idx - (size_t)r * INH);
    int bx   = r >> 5;
    int gate = (r >> 3) & 3;
    int jl   = r & 7;
    int j    = bx * 8 + jl;
    const float* W = (gate == 0) ? Wf : (gate == 1) ? Wi : (gate == 2) ? Wc : Wo;
    float v = W[(size_t)j * INH + k];
    __nv_bfloat16 hi = __float2bfloat16(v);
    g_Wrhi[idx] = hi;
    g_Wrlo[idx] = __float2bfloat16(v - __bfloat162float(hi));
}

__global__ void conv_bias(const float* __restrict__ bf, const float* __restrict__ bi,
                          const float* __restrict__ bc, const float* __restrict__ bo)
{
    int r = blockIdx.x * 256 + threadIdx.x;
    if (r < NG) {
        int bx = r >> 5, gate = (r >> 3) & 3, jl = r & 7;
        int j = bx * 8 + jl;
        const float* b = (gate == 0) ? bf : (gate == 1) ? bi : (gate == 2) ? bc : bo;
        g_biasr[r] = b[j];
    }
}

// x -> bf16 hi/lo planes, stored in the OUTPUT buffer as scratch (exact fit:
// 2 * BB*TT*IN * 2B = BB*TT*OUT * 4B). k3_out overwrites it afterwards.
__global__ void conv_x(const float* __restrict__ x,
                       __nv_bfloat16* __restrict__ xhi,
                       __nv_bfloat16* __restrict__ xlo)
{
    size_t idx = (size_t)blockIdx.x * 256 + threadIdx.x;   // over BB*TT*IN
    float v = x[idx];
    __nv_bfloat16 hi = __float2bfloat16(v);
    xhi[idx] = hi;
    xlo[idx] = __float2bfloat16(v - __bfloat162float(hi));
}

// ---------------- cp.async chunk issue ----------------------------------------
// per-thread maps (256 threads):
//   A: row = tid>>1, half-col = (tid&1)*32 elems -> 4x 16B per plane
//   B: row = tid>>3, col = (tid&7)*8 elems       -> 1x 16B per plane
__device__ __forceinline__ void issue_chunk(
    uint32_t stage,
    const __nv_bfloat16* aH, const __nv_bfloat16* aL,
    const __nv_bfloat16* bH, const __nv_bfloat16* bL,
    uint32_t saoff, uint32_t sboff)
{
    #pragma unroll
    for (int q = 0; q < 4; q++) {
        cpa(stage + ST_A_H + saoff + q * 16, aH + q * 8);
        cpa(stage + ST_A_L + saoff + q * 16, aL + q * 8);
    }
    cpa(stage + ST_B_H + sboff, bH);
    cpa(stage + ST_B_L + sboff, bL);
}

// ---------------- fragment loads + MMA on one stage ---------------------------
__device__ __forceinline__ void mma_stage(uint32_t stage, int w, int lane, float acc[4][4])
{
    const int seg = lane >> 3, lr = lane & 7;
    const int ar  = w * 16 + (seg & 1) * 8 + lr;   // A row
    const int ac  = (seg >> 1) * 8;                // A col offset within k16
    const int bn  = (seg >> 1) * 8 + lr;           // B n-row
    const int bk  = (seg & 1) * 8;                 // B k offset within k16

    #pragma unroll
    for (int ks = 0; ks < 4; ks++) {
        const int kb0 = ks * 16;
        const uint32_t aoff  = (uint32_t)((ar * SPAD + kb0 + ac) * 2);
        const uint32_t b0off = (uint32_t)((bn * SPAD + kb0 + bk) * 2);
        const uint32_t b1off = (uint32_t)(((bn + 16) * SPAD + kb0 + bk) * 2);

        uint32_t ah[4], al[4], bh0[4], bh1[4], bl0[4], bl1[4];
        ldm4(ah,  stage + ST_A_H + aoff);
        ldm4(al,  stage + ST_A_L + aoff);
        ldm4(bh0, stage + ST_B_H + b0off);
        ldm4(bh1, stage + ST_B_H + b1off);
        ldm4(bl0, stage + ST_B_L + b0off);
        ldm4(bl1, stage + ST_B_L + b1off);

        mma_bf16(acc[0], ah, bh0 + 0); mma_bf16(acc[0], ah, bl0 + 0); mma_bf16(acc[0], al, bh0 + 0);
        mma_bf16(acc[1], ah, bh0 + 2); mma_bf16(acc[1], ah, bl0 + 2); mma_bf16(acc[1], al, bh0 + 2);
        mma_bf16(acc[2], ah, bh1 + 0); mma_bf16(acc[2], ah, bl1 + 0); mma_bf16(acc[2], al, bh1 + 0);
        mma_bf16(acc[3], ah, bh1 + 2); mma_bf16(acc[3], ah, bl1 + 2); mma_bf16(acc[3], al, bh1 + 2);
    }
}

// ---------------- one pipelined phase over nch chunks -------------------------
__device__ __forceinline__ void run_phase(
    uint32_t sbase,
    const __nv_bfloat16* aH0, const __nv_bfloat16* aL0,   // chunk-0 A srcs (thread-offset applied)
    const __nv_bfloat16* bH0, const __nv_bfloat16* bL0,   // chunk-0 B srcs
    uint32_t saoff, uint32_t sboff,
    int nch, int w, int lane, float acc[4][4])
{
    #pragma unroll
    for (int s = 0; s < 3; s++) {
        issue_chunk(sbase + s * STAGE, aH0 + s * KC, aL0 + s * KC,
                    bH0 + s * KC, bL0 + s * KC, saoff, sboff);
        CP_COMMIT();
    }
    for (int c = 0; c < nch; c++) {
        CP_WAIT2();                 // chunk c landed (<=2 newer groups pending)
        __syncthreads();            // all warps done reading stage (c-1)%4
        if (c + 3 < nch)
            issue_chunk(sbase + ((c + 3) & 3) * STAGE,
                        aH0 + (c + 3) * KC, aL0 + (c + 3) * KC,
                        bH0 + (c + 3) * KC, bL0 + (c + 3) * KC, saoff, sboff);
        CP_COMMIT();                // empty group at tail keeps counts aligned
        mma_stage(sbase + (c & 3) * STAGE, w, lane, acc);
    }
}

// ---------------- persistent recurrent kernel --------------------------------
__global__ void __launch_bounds__(256, 1) k_persist(
    const __nv_bfloat16* __restrict__ xhi, const __nv_bfloat16* __restrict__ xlo)
{
    extern __shared__ char smem[];
    __shared__ float bias_s[32];

    const int tid  = threadIdx.x;
    const int w    = tid >> 5;
    const int lane = tid & 31;
    const int g    = lane >> 2;
    const int t2   = lane & 3;
    const int n0   = blockIdx.x * 32;
    const int j0   = blockIdx.x * 8;

    const int arow  = tid >> 1;
    const int ahalf = (tid & 1) * 32;            // elems
    const int brow  = tid >> 3;
    const int bcol  = (tid & 7) * 8;             // elems
    const uint32_t saoff = (uint32_t)((arow * SPAD + ahalf) * 2);
    const uint32_t sboff = (uint32_t)((brow * SPAD + bcol) * 2);
    const uint32_t sbase = (uint32_t)__cvta_generic_to_shared(smem);

    if (tid < 32) bias_s[tid] = g_biasr[n0 + tid];

    const __nv_bfloat16* bWxH = g_Wrhi + (size_t)(n0 + brow) * INH + bcol;
    const __nv_bfloat16* bWxL = g_Wrlo + (size_t)(n0 + brow) * INH + bcol;
    const __nv_bfloat16* bWhH = bWxH + IN;
    const __nv_bfloat16* bWhL = bWxL + IN;

    float creg[2][2];
    creg[0][0] = creg[0][1] = creg[1][0] = creg[1][1] = 0.f;

    unsigned gen_cap = 0;   // meaningful on tid 0 only

    for (int t = 0; t < TT; t++) {
        float acc[4][4];
        #pragma unroll
        for (int nt = 0; nt < 4; nt++)
            #pragma unroll
            for (int i = 0; i < 4; i++) acc[nt][i] = 0.f;

        // ---- X phase (8 chunks; independent of h_{t-1}) ----
        {
            const __nv_bfloat16* aH0 = xhi + ((size_t)arow * TT + t) * IN + ahalf;
            const __nv_bfloat16* aL0 = xlo + ((size_t)arow * TT + t) * IN + ahalf;
            run_phase(sbase, aH0, aL0, bWxH, bWxL, saoff, sboff, IN / KC, w, lane, acc);
        }

        if (t > 0) {
            // ---- wait: all blocks wrote h_{t-1} ----
            if (tid == 0) {
                while (*(volatile unsigned*)&g_bar_gen == gen_cap) {}
            }
            __syncthreads();
            // ---- H phase (16 chunks) ----
            const __nv_bfloat16* aH0 = g_hshi + ((size_t)arow * TT + (t - 1)) * HH + ahalf;
            const __nv_bfloat16* aL0 = g_hslo + ((size_t)arow * TT + (t - 1)) * HH + ahalf;
            run_phase(sbase, aH0, aL0, bWhH, bWhL, saoff, sboff, HH / KC, w, lane, acc);
        }

        // ---- fused LSTM cell epilogue ----
        #pragma unroll
        for (int dr = 0; dr < 2; dr++) {
            const int b_  = w * 16 + g + dr * 8;
            const int ci0 = dr * 2;
            const int jlA = 2 * t2;

            float hn2[2];
            #pragma unroll
            for (int dc = 0; dc < 2; dc++) {
                const int jl = jlA + dc;
                const int ci = ci0 + dc;
                const float fp = acc[0][ci] + bias_s[jl];
                const float ip = acc[1][ci] + bias_s[8 + jl];
                const float cp = acc[2][ci] + bias_s[16 + jl];
                const float op = acc[3][ci] + bias_s[24 + jl];
                const float cn = sigm(fp) * creg[dr][dc] + sigm(ip) * tanhf(cp);
                creg[dr][dc] = cn;
                hn2[dc] = sigm(op) * tanhf(cn);
            }
            const size_t ho = ((size_t)b_ * TT + t) * HH + j0 + jlA;
            __nv_bfloat16 h0 = __float2bfloat16(hn2[0]);
            __nv_bfloat16 h1 = __float2bfloat16(hn2[1]);
            __nv_bfloat162 hhi; hhi.x = h0; hhi.y = h1;
            __nv_bfloat162 hlo;
            hlo.x = __float2bfloat16(hn2[0] - __bfloat162float(h0));
            hlo.y = __float2bfloat16(hn2[1] - __bfloat162float(h1));
            __stcg((unsigned*)(g_hshi + ho), *(const unsigned*)&hhi);
            __stcg((unsigned*)(g_hslo + ho), *(const unsigned*)&hlo);
        }

        // ---- arrive (non-blocking); wait overlapped with next X phase ----
        if (t < TT - 1) {
            __threadfence();
            __syncthreads();
            if (tid == 0) {
                gen_cap = *(volatile unsigned*)&g_bar_gen;   // capture BEFORE arriving
                if (atomicAdd(&g_bar_count, 1u) == NBLK - 1) {
                    g_bar_count = 0;
                    __threadfence();
                    atomicAdd(&g_bar_gen, 1u);
                }
            }
        }
    }
}

// ---------------- kernel 3: out = hs @ W_out^T + b_out (fp32 SIMT) -----------
__global__ void __launch_bounds__(256, 2) k3_out(
                       const float* __restrict__ Wout,
                       const float* __restrict__ bout,
                       float* __restrict__ out)
{
    __shared__ float As[8][128];
    __shared__ float Bs[8][128];

    const int m0 = blockIdx.x * 128;
    const int n0 = blockIdx.y * 128;
    const int tid = threadIdx.x;
    const int lr = tid >> 1;
    const int lk = (tid & 1) * 4;

    const __nv_bfloat16* Ahp = g_hshi + (size_t)(m0 + lr) * HH;
    const __nv_bfloat16* Alp = g_hslo + (size_t)(m0 + lr) * HH;
    const float* Brow = Wout + (size_t)(n0 + lr) * HH;

    float acc[8][8];
    #pragma unroll
    for (int i = 0; i < 8; i++)
        #pragma unroll
        for (int j = 0; j < 8; j++) acc[i][j] = 0.f;

    const int r0 = (tid >> 4) * 8;
    const int c0 = (tid & 15) * 8;

    for (int k0 = 0; k0 < HH; k0 += 8) {
        const uint2 rh = *(const uint2*)(Ahp + k0 + lk);
        const uint2 rl = *(const uint2*)(Alp + k0 + lk);
        const __nv_bfloat162 h01 = *(const __nv_bfloat162*)&rh.x;
        const __nv_bfloat162 h23 = *(const __nv_bfloat162*)&rh.y;
        const __nv_bfloat162 l01 = *(const __nv_bfloat162*)&rl.x;
        const __nv_bfloat162 l23 = *(const __nv_bfloat162*)&rl.y;
        float4 av;
        av.x = __bfloat162float(h01.x) + __bfloat162float(l01.x);
        av.y = __bfloat162float(h01.y) + __bfloat162float(l01.y);
        av.z = __bfloat162float(h23.x) + __bfloat162float(l23.x);
        av.w = __bfloat162float(h23.y) + __bfloat162float(l23.y);
        const float4 bv = *(const float4*)(Brow + k0 + lk);
        __syncthreads();
        As[lk + 0][lr] = av.x; As[lk + 1][lr] = av.y; As[lk + 2][lr] = av.z; As[lk + 3][lr] = av.w;
        Bs[lk + 0][lr] = bv.x; Bs[lk + 1][lr] = bv.y; Bs[lk + 2][lr] = bv.z; Bs[lk + 3][lr] = bv.w;
        __syncthreads();
        #pragma unroll
        for (int k = 0; k < 8; k++) {
            float4 a0 = *(const float4*)&As[k][r0];
            float4 a1 = *(const float4*)&As[k][r0 + 4];
            float4 b0 = *(const float4*)&Bs[k][c0];
            float4 b1 = *(const float4*)&Bs[k][c0 + 4];
            float ar[8] = {a0.x, a0.y, a0.z, a0.w, a1.x, a1.y, a1.z, a1.w};
            float br[8] = {b0.x, b0.y, b0.z, b0.w, b1.x, b1.y, b1.z, b1.w};
            #pragma unroll
            for (int i = 0; i < 8; i++)
                #pragma unroll
                for (int j = 0; j < 8; j++) acc[i][j] += ar[i] * br[j];
        }
    }

    #pragma unroll
    for (int i = 0; i < 8; i++) {
        float* Crow = out + (size_t)(m0 + r0 + i) * OUT + n0;
        #pragma unroll
        for (int j = 0; j < 8; j++) Crow[c0 + j] = acc[i][j] + bout[n0 + c0 + j];
    }
}

// ---------------- launch -----------------------------------------------------
extern "C" void kernel_launch(void* const* d_in, const int* in_sizes, int n_in,
                              void* d_out, int out_size)
{
    const float* x    = (const float*)d_in[0];
    const float* Wf   = (const float*)d_in[1];
    const float* bf   = (const float*)d_in[2];
    const float* Wi   = (const float*)d_in[3];
    const float* bi   = (const float*)d_in[4];
    const float* Wc   = (const float*)d_in[5];
    const float* bc   = (const float*)d_in[6];
    const float* Wo   = (const float*)d_in[7];
    const float* bo   = (const float*)d_in[8];
    const float* Wout = (const float*)d_in[9];
    const float* bout = (const float*)d_in[10];
    float* out = (float*)d_out;

    // x hi/lo bf16 planes live in d_out as scratch (exact size match);
    // k3_out overwrites d_out at the end of every launch.
    __nv_bfloat16* xhi = (__nv_bfloat16*)d_out;
    __nv_bfloat16* xlo = xhi + (size_t)BB * TT * IN;

    cudaFuncSetAttribute(k_persist, cudaFuncAttributeMaxDynamicSharedMemorySize, SMEM_DYN);

    conv_w   <<<(NG * INH) / 256, 256>>>(Wf, Wi, Wc, Wo);
    conv_bias<<<16, 256>>>(bf, bi, bc, bo);
    conv_x   <<<(BB * TT * IN) / 256, 256>>>(x, xhi, xlo);

    k_persist<<<NBLK, 256, SMEM_DYN>>>(xhi, xlo);

    k3_out<<<dim3((BB * TT) / 128, OUT / 128), 256>>>(Wout, bout, out);
}

// round 11
// speedup vs baseline: 2.3902x; 1.4708x over previous
#include <cuda_runtime.h>
#include <cuda_fp16.h>
#include <math.h>
#include <stdint.h>

#define BB   128
#define TT   256
#define IN   512
#define HH   1024
#define OUT  512
#define NG   4096
#define INH  1536
#define KC   64
#define SPAD 72        // smem row stride in fp16 elems (64 + 8 pad), 144B
#define NBLK 128       // persistent grid (1 block/SM, co-resident)

// stage layout (bytes): A single plane + B hi/lo
#define ST_A   0
#define ST_B_H 18432                 // 128*72*2
#define ST_B_L 23040                 // +32*72*2
#define STAGE  27648
#define NSTAGE 4
#define SMEM_DYN (NSTAGE * STAGE)    // 110592

// ---------------- static device scratch (~90 MB) ------------------------------
__device__ __half g_Wrhi[(size_t)NG * INH];   // r = bx*32 + gate*8 + jl
__device__ __half g_Wrlo[(size_t)NG * INH];
__device__ float  g_biasr[NG];
__device__ __half g_hs[(size_t)BB * TT * HH];  // [b][t][j], single fp16 plane
__device__ unsigned g_bar_count;
__device__ unsigned g_bar_gen;

__device__ __forceinline__ float sigm(float v) { return 1.f / (1.f + expf(-v)); }

__device__ __forceinline__ void mma_f16(float* c, const uint32_t* a, const uint32_t* b) {
    asm volatile(
        "mma.sync.aligned.m16n8k16.row.col.f32.f16.f16.f32 "
        "{%0,%1,%2,%3}, {%4,%5,%6,%7}, {%8,%9}, {%0,%1,%2,%3};"
        : "+f"(c[0]), "+f"(c[1]), "+f"(c[2]), "+f"(c[3])
        : "r"(a[0]), "r"(a[1]), "r"(a[2]), "r"(a[3]), "r"(b[0]), "r"(b[1]));
}

__device__ __forceinline__ void ldm4(uint32_t* r, uint32_t addr) {
    asm volatile("ldmatrix.sync.aligned.m8n8.x4.shared.b16 {%0,%1,%2,%3}, [%4];"
        : "=r"(r[0]), "=r"(r[1]), "=r"(r[2]), "=r"(r[3]) : "r"(addr));
}

__device__ __forceinline__ void cpa(uint32_t dst, const void* src) {
    asm volatile("cp.async.cg.shared.global [%0], [%1], 16;" :: "r"(dst), "l"(src));
}
#define CP_COMMIT() asm volatile("cp.async.commit_group;")
#define CP_WAIT2()  asm volatile("cp.async.wait_group 2;")

// ---------------- conversion kernels -----------------------------------------
__global__ void conv_w(const float* __restrict__ Wf, const float* __restrict__ Wi,
                       const float* __restrict__ Wc, const float* __restrict__ Wo)
{
    size_t idx = (size_t)blockIdx.x * 256 + threadIdx.x;   // over NG*INH
    int r = (int)(idx / INH);
    int k = (int)(idx - (size_t)r * INH);
    int bx   = r >> 5;
    int gate = (r >> 3) & 3;
    int jl   = r & 7;
    int j    = bx * 8 + jl;
    const float* W = (gate == 0) ? Wf : (gate == 1) ? Wi : (gate == 2) ? Wc : Wo;
    float v = W[(size_t)j * INH + k];
    __half hi = __float2half(v);
    g_Wrhi[idx] = hi;
    g_Wrlo[idx] = __float2half(v - __half2float(hi));
}

__global__ void conv_bias(const float* __restrict__ bf, const float* __restrict__ bi,
                          const float* __restrict__ bc, const float* __restrict__ bo)
{
    int r = blockIdx.x * 256 + threadIdx.x;
    if (r < NG) {
        int bx = r >> 5, gate = (r >> 3) & 3, jl = r & 7;
        int j = bx * 8 + jl;
        const float* b = (gate == 0) ? bf : (gate == 1) ? bi : (gate == 2) ? bc : bo;
        g_biasr[r] = b[j];
    }
}

// x -> single fp16 plane, stored in the OUTPUT buffer as scratch (33.5 MB of
// the 67 MB d_out). k3_out overwrites d_out afterwards.
__global__ void conv_x(const float* __restrict__ x, __half* __restrict__ xh)
{
    size_t idx = (size_t)blockIdx.x * 256 + threadIdx.x;   // over BB*TT*IN
    xh[idx] = __float2half(x[idx]);
}

// ---------------- cp.async chunk issue ----------------------------------------
// per-thread maps (256 threads):
//   A: row = tid>>1, half-col = (tid&1)*32 elems -> 4x 16B
//   B: row = tid>>3, col = (tid&7)*8 elems       -> 1x 16B per plane
__device__ __forceinline__ void issue_chunk(
    uint32_t stage, const __half* aS,
    const __half* bH, const __half* bL,
    uint32_t saoff, uint32_t sboff)
{
    #pragma unroll
    for (int q = 0; q < 4; q++)
        cpa(stage + ST_A + saoff + q * 16, aS + q * 8);
    cpa(stage + ST_B_H + sboff, bH);
    cpa(stage + ST_B_L + sboff, bL);
}

// ---------------- fragment loads + MMA on one stage ---------------------------
__device__ __forceinline__ void mma_stage(uint32_t stage, int w, int lane, float acc[4][4])
{
    const int seg = lane >> 3, lr = lane & 7;
    const int ar  = w * 16 + (seg & 1) * 8 + lr;   // A row
    const int ac  = (seg >> 1) * 8;                // A col offset within k16
    const int bn  = (seg >> 1) * 8 + lr;           // B n-row
    const int bk  = (seg & 1) * 8;                 // B k offset within k16

    #pragma unroll
    for (int ks = 0; ks < 4; ks++) {
        const int kb0 = ks * 16;
        const uint32_t aoff  = (uint32_t)((ar * SPAD + kb0 + ac) * 2);
        const uint32_t b0off = (uint32_t)((bn * SPAD + kb0 + bk) * 2);
        const uint32_t b1off = (uint32_t)(((bn + 16) * SPAD + kb0 + bk) * 2);

        uint32_t a[4], bh0[4], bh1[4], bl0[4], bl1[4];
        ldm4(a,   stage + ST_A   + aoff);
        ldm4(bh0, stage + ST_B_H + b0off);
        ldm4(bh1, stage + ST_B_H + b1off);
        ldm4(bl0, stage + ST_B_L + b0off);
        ldm4(bl1, stage + ST_B_L + b1off);

        mma_f16(acc[0], a, bh0 + 0); mma_f16(acc[1], a, bh0 + 2);
        mma_f16(acc[2], a, bh1 + 0); mma_f16(acc[3], a, bh1 + 2);
        mma_f16(acc[0], a, bl0 + 0); mma_f16(acc[1], a, bl0 + 2);
        mma_f16(acc[2], a, bl1 + 0); mma_f16(acc[3], a, bl1 + 2);
    }
}

// ---------------- one pipelined phase over nch chunks -------------------------
__device__ __forceinline__ void run_phase(
    uint32_t sbase, const __half* aS0,
    const __half* bH0, const __half* bL0,
    uint32_t saoff, uint32_t sboff,
    int nch, int w, int lane, float acc[4][4])
{
    #pragma unroll
    for (int s = 0; s < 3; s++) {
        issue_chunk(sbase + s * STAGE, aS0 + s * KC, bH0 + s * KC, bL0 + s * KC,
                    saoff, sboff);
        CP_COMMIT();
    }
    for (int c = 0; c < nch; c++) {
        CP_WAIT2();                 // chunk c landed (<=2 newer groups pending)
        __syncthreads();            // all warps done reading stage (c-1)%4
        if (c + 3 < nch)
            issue_chunk(sbase + ((c + 3) & 3) * STAGE,
                        aS0 + (c + 3) * KC, bH0 + (c + 3) * KC, bL0 + (c + 3) * KC,
                        saoff, sboff);
        CP_COMMIT();                // empty group at tail keeps counts aligned
        mma_stage(sbase + (c & 3) * STAGE, w, lane, acc);
    }
}

// ---------------- persistent recurrent kernel --------------------------------
__global__ void __launch_bounds__(256, 1) k_persist(const __half* __restrict__ xh)
{
    extern __shared__ char smem[];
    __shared__ float bias_s[32];

    const int tid  = threadIdx.x;
    const int w    = tid >> 5;
    const int lane = tid & 31;
    const int g    = lane >> 2;
    const int t2   = lane & 3;
    const int n0   = blockIdx.x * 32;
    const int j0   = blockIdx.x * 8;

    const int arow  = tid >> 1;
    const int ahalf = (tid & 1) * 32;            // elems
    const int brow  = tid >> 3;
    const int bcol  = (tid & 7) * 8;             // elems
    const uint32_t saoff = (uint32_t)((arow * SPAD + ahalf) * 2);
    const uint32_t sboff = (uint32_t)((brow * SPAD + bcol) * 2);
    const uint32_t sbase = (uint32_t)__cvta_generic_to_shared(smem);

    if (tid < 32) bias_s[tid] = g_biasr[n0 + tid];

    const __half* bWxH = g_Wrhi + (size_t)(n0 + brow) * INH + bcol;
    const __half* bWxL = g_Wrlo + (size_t)(n0 + brow) * INH + bcol;
    const __half* bWhH = bWxH + IN;
    const __half* bWhL = bWxL + IN;

    float creg[2][2];
    creg[0][0] = creg[0][1] = creg[1][0] = creg[1][1] = 0.f;

    unsigned gen_cap = 0;   // meaningful on tid 0 only

    for (int t = 0; t < TT; t++) {
        float acc[4][4];
        #pragma unroll
        for (int nt = 0; nt < 4; nt++)
            #pragma unroll
            for (int i = 0; i < 4; i++) acc[nt][i] = 0.f;

        // ---- X phase (8 chunks; independent of h_{t-1}) ----
        {
            const __half* aS0 = xh + ((size_t)arow * TT + t) * IN + ahalf;
            run_phase(sbase, aS0, bWxH, bWxL, saoff, sboff, IN / KC, w, lane, acc);
        }

        if (t > 0) {
            // ---- wait: all blocks wrote h_{t-1} ----
            if (tid == 0) {
                while (*(volatile unsigned*)&g_bar_gen == gen_cap) {}
            }
            __syncthreads();
            // ---- H phase (16 chunks) ----
            const __half* aS0 = g_hs + ((size_t)arow * TT + (t - 1)) * HH + ahalf;
            run_phase(sbase, aS0, bWhH, bWhL, saoff, sboff, HH / KC, w, lane, acc);
        }

        // ---- fused LSTM cell epilogue ----
        #pragma unroll
        for (int dr = 0; dr < 2; dr++) {
            const int b_  = w * 16 + g + dr * 8;
            const int ci0 = dr * 2;
            const int jlA = 2 * t2;

            float hn2[2];
            #pragma unroll
            for (int dc = 0; dc < 2; dc++) {
                const int jl = jlA + dc;
                const int ci = ci0 + dc;
                const float fp = acc[0][ci] + bias_s[jl];
                const float ip = acc[1][ci] + bias_s[8 + jl];
                const float cp = acc[2][ci] + bias_s[16 + jl];
                const float op = acc[3][ci] + bias_s[24 + jl];
                const float cn = sigm(fp) * creg[dr][dc] + sigm(ip) * tanhf(cp);
                creg[dr][dc] = cn;
                hn2[dc] = sigm(op) * tanhf(cn);
            }
            const size_t ho = ((size_t)b_ * TT + t) * HH + j0 + jlA;
            __half2 hp;
            hp.x = __float2half(hn2[0]);
            hp.y = __float2half(hn2[1]);
            __stcg((unsigned*)(g_hs + ho), *(const unsigned*)&hp);
        }

        // ---- arrive (non-blocking); wait overlapped with next X phase ----
        if (t < TT - 1) {
            __threadfence();
            __syncthreads();
            if (tid == 0) {
                gen_cap = *(volatile unsigned*)&g_bar_gen;   // capture BEFORE arriving
                if (atomicAdd(&g_bar_count, 1u) == NBLK - 1) {
                    g_bar_count = 0;
                    __threadfence();
                    atomicAdd(&g_bar_gen, 1u);
                }
            }
        }
    }
}

// ---------------- kernel 3: out = hs @ W_out^T + b_out (fp32 SIMT) -----------
__global__ void __launch_bounds__(256, 2) k3_out(
                       const float* __restrict__ Wout,
                       const float* __restrict__ bout,
                       float* __restrict__ out)
{
    __shared__ float As[8][128];
    __shared__ float Bs[8][128];

    const int m0 = blockIdx.x * 128;
    const int n0 = blockIdx.y * 128;
    const int tid = threadIdx.x;
    const int lr = tid >> 1;
    const int lk = (tid & 1) * 4;

    const __half* Ahp = g_hs + (size_t)(m0 + lr) * HH;
    const float* Brow = Wout + (size_t)(n0 + lr) * HH;

    float acc[8][8];
    #pragma unroll
    for (int i = 0; i < 8; i++)
        #pragma unroll
        for (int j = 0; j < 8; j++) acc[i][j] = 0.f;

    const int r0 = (tid >> 4) * 8;
    const int c0 = (tid & 15) * 8;

    for (int k0 = 0; k0 < HH; k0 += 8) {
        const uint2 rh = *(const uint2*)(Ahp + k0 + lk);
        const __half2 h01 = *(const __half2*)&rh.x;
        const __half2 h23 = *(const __half2*)&rh.y;
        float4 av;
        av.x = __half2float(h01.x);
        av.y = __half2float(h01.y);
        av.z = __half2float(h23.x);
        av.w = __half2float(h23.y);
        const float4 bv = *(const float4*)(Brow + k0 + lk);
        __syncthreads();
        As[lk + 0][lr] = av.x; As[lk + 1][lr] = av.y; As[lk + 2][lr] = av.z; As[lk + 3][lr] = av.w;
        Bs[lk + 0][lr] = bv.x; Bs[lk + 1][lr] = bv.y; Bs[lk + 2][lr] = bv.z; Bs[lk + 3][lr] = bv.w;
        __syncthreads();
        #pragma unroll
        for (int k = 0; k < 8; k++) {
            float4 a0 = *(const float4*)&As[k][r0];
            float4 a1 = *(const float4*)&As[k][r0 + 4];
            float4 b0 = *(const float4*)&Bs[k][c0];
            float4 b1 = *(const float4*)&Bs[k][c0 + 4];
            float ar[8] = {a0.x, a0.y, a0.z, a0.w, a1.x, a1.y, a1.z, a1.w};
            float br[8] = {b0.x, b0.y, b0.z, b0.w, b1.x, b1.y, b1.z, b1.w};
            #pragma unroll
            for (int i = 0; i < 8; i++)
                #pragma unroll
                for (int j = 0; j < 8; j++) acc[i][j] += ar[i] * br[j];
        }
    }

    #pragma unroll
    for (int i = 0; i < 8; i++) {
        float* Crow = out + (size_t)(m0 + r0 + i) * OUT + n0;
        #pragma unroll
        for (int j = 0; j < 8; j++) Crow[c0 + j] = acc[i][j] + bout[n0 + c0 + j];
    }
}

// ---------------- launch -----------------------------------------------------
extern "C" void kernel_launch(void* const* d_in, const int* in_sizes, int n_in,
                              void* d_out, int out_size)
{
    const float* x    = (const float*)d_in[0];
    const float* Wf   = (const float*)d_in[1];
    const float* bf   = (const float*)d_in[2];
    const float* Wi   = (const float*)d_in[3];
    const float* bi   = (const float*)d_in[4];
    const float* Wc   = (const float*)d_in[5];
    const float* bc   = (const float*)d_in[6];
    const float* Wo   = (const float*)d_in[7];
    const float* bo   = (const float*)d_in[8];
    const float* Wout = (const float*)d_in[9];
    const float* bout = (const float*)d_in[10];
    float* out = (float*)d_out;

    // x fp16 plane lives in d_out as scratch (33.5 MB of 67 MB);
    // k3_out overwrites d_out at the end of every launch.
    __half* xh = (__half*)d_out;

    cudaFuncSetAttribute(k_persist, cudaFuncAttributeMaxDynamicSharedMemorySize, SMEM_DYN);

    conv_w   <<<(NG * INH) / 256, 256>>>(Wf, Wi, Wc, Wo);
    conv_bias<<<16, 256>>>(bf, bi, bc, bo);
    conv_x   <<<(BB * TT * IN) / 256, 256>>>(x, xh);

    k_persist<<<NBLK, 256, SMEM_DYN>>>(xh);

    k3_out<<<dim3((BB * TT) / 128, OUT / 128), 256>>>(Wout, bout, out);
}

// round 15
// speedup vs baseline: 2.4072x; 1.0071x over previous
#include <cuda_runtime.h>
#include <cuda_fp16.h>
#include <math.h>
#include <stdint.h>

#define BB   128
#define TT   256
#define IN   512
#define HH   1024
#define OUT  512
#define NG   4096
#define INH  1536
#define KC   64
#define SPAD 72        // smem row stride in fp16 elems (64 + 8 pad), 144B
#define NBLK 128       // persistent grid (1 block/SM, co-resident)

// stage layout (bytes): A single plane + B hi/lo
#define ST_A   0
#define ST_B_H 18432                 // 128*72*2
#define ST_B_L 23040                 // +32*72*2
#define STAGE  27648
#define NSTAGE 4
#define SMEM_DYN (NSTAGE * STAGE)    // 110592

// ---------------- static device scratch (~90 MB) ------------------------------
__device__ __half g_Wrhi[(size_t)NG * INH];   // r = bx*32 + gate*8 + jl
__device__ __half g_Wrlo[(size_t)NG * INH];
__device__ float  g_biasr[NG];
__device__ __half g_hs[(size_t)BB * TT * HH];  // [b][t][j], single fp16 plane
__device__ unsigned g_bar_count;
__device__ unsigned g_bar_gen;

__device__ __forceinline__ float sigm(float v) { return 1.f / (1.f + expf(-v)); }

__device__ __forceinline__ void mma_f16(float* c, const uint32_t* a, const uint32_t* b) {
    asm volatile(
        "mma.sync.aligned.m16n8k16.row.col.f32.f16.f16.f32 "
        "{%0,%1,%2,%3}, {%4,%5,%6,%7}, {%8,%9}, {%0,%1,%2,%3};"
        : "+f"(c[0]), "+f"(c[1]), "+f"(c[2]), "+f"(c[3])
        : "r"(a[0]), "r"(a[1]), "r"(a[2]), "r"(a[3]), "r"(b[0]), "r"(b[1]));
}

__device__ __forceinline__ void ldm4(uint32_t* r, uint32_t addr) {
    asm volatile("ldmatrix.sync.aligned.m8n8.x4.shared.b16 {%0,%1,%2,%3}, [%4];"
        : "=r"(r[0]), "=r"(r[1]), "=r"(r[2]), "=r"(r[3]) : "r"(addr));
}

__device__ __forceinline__ void cpa(uint32_t dst, const void* src) {
    asm volatile("cp.async.cg.shared.global [%0], [%1], 16;" :: "r"(dst), "l"(src));
}
#define CP_COMMIT() asm volatile("cp.async.commit_group;")
#define CP_WAIT2()  asm volatile("cp.async.wait_group 2;")

// ---------------- conversion kernels -----------------------------------------
__global__ void conv_w(const float* __restrict__ Wf, const float* __restrict__ Wi,
                       const float* __restrict__ Wc, const float* __restrict__ Wo)
{
    size_t idx = (size_t)blockIdx.x * 256 + threadIdx.x;   // over NG*INH
    int r = (int)(idx / INH);
    int k = (int)(idx - (size_t)r * INH);
    int bx   = r >> 5;
    int gate = (r >> 3) & 3;
    int jl   = r & 7;
    int j    = bx * 8 + jl;
    const float* W = (gate == 0) ? Wf : (gate == 1) ? Wi : (gate == 2) ? Wc : Wo;
    float v = W[(size_t)j * INH + k];
    __half hi = __float2half(v);
    g_Wrhi[idx] = hi;
    g_Wrlo[idx] = __float2half(v - __half2float(hi));
}

__global__ void conv_bias(const float* __restrict__ bf, const float* __restrict__ bi,
                          const float* __restrict__ bc, const float* __restrict__ bo)
{
    int r = blockIdx.x * 256 + threadIdx.x;
    if (r < NG) {
        int bx = r >> 5, gate = (r >> 3) & 3, jl = r & 7;
        int j = bx * 8 + jl;
        const float* b = (gate == 0) ? bf : (gate == 1) ? bi : (gate == 2) ? bc : bo;
        g_biasr[r] = b[j];
    }
}

// x -> single fp16 plane, stored in the OUTPUT buffer as scratch.
__global__ void conv_x(const float* __restrict__ x, __half* __restrict__ xh)
{
    size_t idx = (size_t)blockIdx.x * 256 + threadIdx.x;   // over BB*TT*IN
    xh[idx] = __float2half(x[idx]);
}

// ---------------- cp.async chunk issue ----------------------------------------
__device__ __forceinline__ void issue_chunk(
    uint32_t stage, const __half* aS,
    const __half* bH, const __half* bL,
    uint32_t saoff, uint32_t sboff)
{
    #pragma unroll
    for (int q = 0; q < 4; q++)
        cpa(stage + ST_A + saoff + q * 16, aS + q * 8);
    cpa(stage + ST_B_H + sboff, bH);
    cpa(stage + ST_B_L + sboff, bL);
}

// ---------------- fragment pipeline -------------------------------------------
struct Frags { uint32_t a[4], bh0[4], bh1[4], bl0[4], bl1[4]; };

__device__ __forceinline__ void load_frags(Frags& f, uint32_t stage, int ks,
                                           uint32_t aoffb, uint32_t b0offb, uint32_t b1offb)
{
    const uint32_t kb = (uint32_t)(ks * 32);   // ks*16 elems * 2B
    ldm4(f.a,   stage + ST_A   + aoffb + kb);
    ldm4(f.bh0, stage + ST_B_H + b0offb + kb);
    ldm4(f.bh1, stage + ST_B_H + b1offb + kb);
    ldm4(f.bl0, stage + ST_B_L + b0offb + kb);
    ldm4(f.bl1, stage + ST_B_L + b1offb + kb);
}

__device__ __forceinline__ void mma_frags(const Frags& f, float acc[4][4])
{
    mma_f16(acc[0], f.a, f.bh0 + 0); mma_f16(acc[1], f.a, f.bh0 + 2);
    mma_f16(acc[2], f.a, f.bh1 + 0); mma_f16(acc[3], f.a, f.bh1 + 2);
    mma_f16(acc[0], f.a, f.bl0 + 0); mma_f16(acc[1], f.a, f.bl0 + 2);
    mma_f16(acc[2], f.a, f.bl1 + 0); mma_f16(acc[3], f.a, f.bl1 + 2);
}

// MMA over one chunk (4 k16-steps) with 2-deep register frag prefetch:
// ldmatrix for ks+1 issues while ks's mmas run. Same arithmetic order as the
// round-11 passing kernel (per-ks mma sequence unchanged).
__device__ __forceinline__ void mma_stage(uint32_t stage,
                                          uint32_t aoffb, uint32_t b0offb, uint32_t b1offb,
                                          float acc[4][4])
{
    Frags f0, f1;
    load_frags(f0, stage, 0, aoffb, b0offb, b1offb);
    #pragma unroll
    for (int ks = 0; ks < 4; ks++) {
        Frags& cur = (ks & 1) ? f1 : f0;
        Frags& nxt = (ks & 1) ? f0 : f1;
        if (ks < 3)
            load_frags(nxt, stage, ks + 1, aoffb, b0offb, b1offb);
        mma_frags(cur, acc);
    }
}

// ---------------- one pipelined phase over nch chunks -------------------------
// Identical stage/sync/wait discipline to the round-11 passing kernel:
// 4-stage ring, one chunk per iteration, issue chunk c+3, wait_group 2.
__device__ __forceinline__ void run_phase(
    uint32_t sbase, const __half* aS0,
    const __half* bH0, const __half* bL0,
    uint32_t saoff, uint32_t sboff,
    uint32_t aoffb, uint32_t b0offb, uint32_t b1offb,
    int nch, float acc[4][4])
{
    #pragma unroll
    for (int s = 0; s < 3; s++) {
        issue_chunk(sbase + s * STAGE, aS0 + s * KC, bH0 + s * KC, bL0 + s * KC,
                    saoff, sboff);
        CP_COMMIT();
    }
    for (int c = 0; c < nch; c++) {
        CP_WAIT2();                 // chunk c landed (<=2 newer groups pending)
        __syncthreads();            // all warps done reading stage (c-1)%4
        if (c + 3 < nch)
            issue_chunk(sbase + ((c + 3) & 3) * STAGE,
                        aS0 + (c + 3) * KC, bH0 + (c + 3) * KC, bL0 + (c + 3) * KC,
                        saoff, sboff);
        CP_COMMIT();                // empty group at tail keeps counts aligned
        mma_stage(sbase + (c & 3) * STAGE, aoffb, b0offb, b1offb, acc);
    }
}

// ---------------- persistent recurrent kernel --------------------------------
__global__ void __launch_bounds__(256, 1) k_persist(const __half* __restrict__ xh)
{
    extern __shared__ char smem[];
    __shared__ float bias_s[32];

    const int tid  = threadIdx.x;
    const int w    = tid >> 5;
    const int lane = tid & 31;
    const int g    = lane >> 2;
    const int t2   = lane & 3;
    const int n0   = blockIdx.x * 32;
    const int j0   = blockIdx.x * 8;

    const int arow  = tid >> 1;
    const int ahalf = (tid & 1) * 32;            // elems
    const int brow  = tid >> 3;
    const int bcol  = (tid & 7) * 8;             // elems
    const uint32_t saoff = (uint32_t)((arow * SPAD + ahalf) * 2);
    const uint32_t sboff = (uint32_t)((brow * SPAD + bcol) * 2);
    const uint32_t sbase = (uint32_t)__cvta_generic_to_shared(smem);

    // fragment base offsets (bytes, ks = 0)
    const int seg = lane >> 3, lr = lane & 7;
    const int ar  = w * 16 + (seg & 1) * 8 + lr;
    const int ac  = (seg >> 1) * 8;
    const int bn  = (seg >> 1) * 8 + lr;
    const int bk  = (seg & 1) * 8;
    const uint32_t aoffb  = (uint32_t)((ar * SPAD + ac) * 2);
    const uint32_t b0offb = (uint32_t)((bn * SPAD + bk) * 2);
    const uint32_t b1offb = (uint32_t)(((bn + 16) * SPAD + bk) * 2);

    if (tid < 32) bias_s[tid] = g_biasr[n0 + tid];

    const __half* bWxH = g_Wrhi + (size_t)(n0 + brow) * INH + bcol;
    const __half* bWxL = g_Wrlo + (size_t)(n0 + brow) * INH + bcol;
    const __half* bWhH = bWxH + IN;
    const __half* bWhL = bWxL + IN;

    float creg[2][2];
    creg[0][0] = creg[0][1] = creg[1][0] = creg[1][1] = 0.f;

    unsigned gen_cap = 0;   // meaningful on tid 0 only

    for (int t = 0; t < TT; t++) {
        float acc[4][4];
        #pragma unroll
        for (int nt = 0; nt < 4; nt++)
            #pragma unroll
            for (int i = 0; i < 4; i++) acc[nt][i] = 0.f;

        // ---- X phase (8 chunks; independent of h_{t-1}) ----
        {
            const __half* aS0 = xh + ((size_t)arow * TT + t) * IN + ahalf;
            run_phase(sbase, aS0, bWxH, bWxL, saoff, sboff,
                      aoffb, b0offb, b1offb, IN / KC, acc);
        }

        if (t > 0) {
            // ---- wait: all blocks wrote h_{t-1} ----
            if (tid == 0) {
                while (*(volatile unsigned*)&g_bar_gen == gen_cap) {}
            }
            __syncthreads();   // orders X-phase final reads before H writes
            // ---- H phase (16 chunks) ----
            const __half* aS0 = g_hs + ((size_t)arow * TT + (t - 1)) * HH + ahalf;
            run_phase(sbase, aS0, bWhH, bWhL, saoff, sboff,
                      aoffb, b0offb, b1offb, HH / KC, acc);
        }

        // ---- fused LSTM cell epilogue ----
        #pragma unroll
        for (int dr = 0; dr < 2; dr++) {
            const int b_  = w * 16 + g + dr * 8;
            const int ci0 = dr * 2;
            const int jlA = 2 * t2;

            float hn2[2];
            #pragma unroll
            for (int dc = 0; dc < 2; dc++) {
                const int jl = jlA + dc;
                const int ci = ci0 + dc;
                const float fp = acc[0][ci] + bias_s[jl];
                const float ip = acc[1][ci] + bias_s[8 + jl];
                const float cp = acc[2][ci] + bias_s[16 + jl];
                const float op = acc[3][ci] + bias_s[24 + jl];
                const float cn = sigm(fp) * creg[dr][dc] + sigm(ip) * tanhf(cp);
                creg[dr][dc] = cn;
                hn2[dc] = sigm(op) * tanhf(cn);
            }
            const size_t ho = ((size_t)b_ * TT + t) * HH + j0 + jlA;
            __half2 hp;
            hp.x = __float2half(hn2[0]);
            hp.y = __float2half(hn2[1]);
            __stcg((unsigned*)(g_hs + ho), *(const unsigned*)&hp);
        }

        // ---- arrive (non-blocking); wait overlapped with next X phase ----
        if (t < TT - 1) {
            __threadfence();
            __syncthreads();   // orders H-phase final reads before next X writes
            if (tid == 0) {
                gen_cap = *(volatile unsigned*)&g_bar_gen;   // capture BEFORE arriving
                if (atomicAdd(&g_bar_count, 1u) == NBLK - 1) {
                    g_bar_count = 0;
                    __threadfence();
                    atomicAdd(&g_bar_gen, 1u);
                }
            }
        }
    }
}

// ---------------- kernel 3: out = hs @ W_out^T + b_out (fp32 SIMT) -----------
__global__ void __launch_bounds__(256, 2) k3_out(
                       const float* __restrict__ Wout,
                       const float* __restrict__ bout,
                       float* __restrict__ out)
{
    __shared__ float As[8][128];
    __shared__ float Bs[8][128];

    const int m0 = blockIdx.x * 128;
    const int n0 = blockIdx.y * 128;
    const int tid = threadIdx.x;
    const int lr = tid >> 1;
    const int lk = (tid & 1) * 4;

    const __half* Ahp = g_hs + (size_t)(m0 + lr) * HH;
    const float* Brow = Wout + (size_t)(n0 + lr) * HH;

    float acc[8][8];
    #pragma unroll
    for (int i = 0; i < 8; i++)
        #pragma unroll
        for (int j = 0; j < 8; j++) acc[i][j] = 0.f;

    const int r0 = (tid >> 4) * 8;
    const int c0 = (tid & 15) * 8;

    for (int k0 = 0; k0 < HH; k0 += 8) {
        const uint2 rh = *(const uint2*)(Ahp + k0 + lk);
        const __half2 h01 = *(const __half2*)&rh.x;
        const __half2 h23 = *(const __half2*)&rh.y;
        float4 av;
        av.x = __half2float(h01.x);
        av.y = __half2float(h01.y);
        av.z = __half2float(h23.x);
        av.w = __half2float(h23.y);
        const float4 bv = *(const float4*)(Brow + k0 + lk);
        __syncthreads();
        As[lk + 0][lr] = av.x; As[lk + 1][lr] = av.y; As[lk + 2][lr] = av.z; As[lk + 3][lr] = av.w;
        Bs[lk + 0][lr] = bv.x; Bs[lk + 1][lr] = bv.y; Bs[lk + 2][lr] = bv.z; Bs[lk + 3][lr] = bv.w;
        __syncthreads();
        #pragma unroll
        for (int k = 0; k < 8; k++) {
            float4 a0 = *(const float4*)&As[k][r0];
            float4 a1 = *(const float4*)&As[k][r0 + 4];
            float4 b0 = *(const float4*)&Bs[k][c0];
            float4 b1 = *(const float4*)&Bs[k][c0 + 4];
            float ar[8] = {a0.x, a0.y, a0.z, a0.w, a1.x, a1.y, a1.z, a1.w};
            float br[8] = {b0.x, b0.y, b0.z, b0.w, b1.x, b1.y, b1.z, b1.w};
            #pragma unroll
            for (int i = 0; i < 8; i++)
                #pragma unroll
                for (int j = 0; j < 8; j++) acc[i][j] += ar[i] * br[j];
        }
    }

    #pragma unroll
    for (int i = 0; i < 8; i++) {
        float* Crow = out + (size_t)(m0 + r0 + i) * OUT + n0;
        #pragma unroll
        for (int j = 0; j < 8; j++) Crow[c0 + j] = acc[i][j] + bout[n0 + c0 + j];
    }
}

// ---------------- launch -----------------------------------------------------
extern "C" void kernel_launch(void* const* d_in, const int* in_sizes, int n_in,
                              void* d_out, int out_size)
{
    const float* x    = (const float*)d_in[0];
    const float* Wf   = (const float*)d_in[1];
    const float* bf   = (const float*)d_in[2];
    const float* Wi   = (const float*)d_in[3];
    const float* bi   = (const float*)d_in[4];
    const float* Wc   = (const float*)d_in[5];
    const float* bc   = (const float*)d_in[6];
    const float* Wo   = (const float*)d_in[7];
    const float* bo   = (const float*)d_in[8];
    const float* Wout = (const float*)d_in[9];
    const float* bout = (const float*)d_in[10];
    float* out = (float*)d_out;

    // x fp16 plane lives in d_out as scratch; k3_out overwrites d_out at the end.
    __half* xh = (__half*)d_out;

    cudaFuncSetAttribute(k_persist, cudaFuncAttributeMaxDynamicSharedMemorySize, SMEM_DYN);

    conv_w   <<<(NG * INH) / 256, 256>>>(Wf, Wi, Wc, Wo);
    conv_bias<<<16, 256>>>(bf, bi, bc, bo);
    conv_x   <<<(BB * TT * IN) / 256, 256>>>(x, xh);

    k_persist<<<NBLK, 256, SMEM_DYN>>>(xh);

    k3_out<<<dim3((BB * TT) / 128, OUT / 128), 256>>>(Wout, bout, out);
}